// round 6
// baseline (speedup 1.0000x reference)
#include <cuda_runtime.h>
#include <cuda_bf16.h>
#include <cstdint>
#include <climits>

// Problem constants
#define BG   64
#define NPG  2048
#define NN   (BG * NPG)      // 131072 nodes
#define EPG  32768
#define EE   (BG * EPG)      // 2097152 edges
#define DD   32
#define KK   1024            // kept per graph
#define BK   (BG * KK)       // 65536 kept total

#define SPLITS 4             // blocks per graph
#define NLOC   (NPG / SPLITS)   // 512 nodes per block
#define CAP    9728          // adjacency capacity per block (mean 8192, +19 sigma)

// Output layout (flattened f32, reference return order)
#define OFF_X5     ((size_t)0)                       // BK*DD
#define OFF_EI     ((size_t)(BK * DD))               // 2*EE
#define OFF_EA     (OFF_EI + (size_t)(2 * EE))       // EE
#define OFF_BATCH  (OFF_EA + (size_t)EE)             // BK
#define OFF_PERM   (OFF_BATCH + (size_t)BK)          // BK
#define OFF_SCORE  (OFF_PERM + (size_t)BK)           // BK

// Scratch (device globals -- no allocation allowed)
__device__ float g_x3[(size_t)NN * DD];   // third-layer output for all nodes
__device__ float g_score[NN];
__device__ int   g_newidx[NN];
__device__ int   g_perm[BK];

// ---------------------------------------------------------------------------
// Fused: per-block CSR build (smem) + edge-order aggregation + score + x3.
// Block b: graph g = b/SPLITS, node range [h*NLOC, (h+1)*NLOC), h = b%SPLITS.
__global__ __launch_bounds__(1024) void fused_kernel(
    const float* __restrict__ x, const int* __restrict__ ei,
    const float* __restrict__ Wr1, const float* __restrict__ Wl1,
    const float* __restrict__ b1,
    const float* __restrict__ Wr2, const float* __restrict__ Wl2,
    const float* __restrict__ b2,
    const float* __restrict__ Wr3, const float* __restrict__ Wl3,
    const float* __restrict__ b3) {
    extern __shared__ int smem[];
    int*   hist = smem;                 // [NLOC] -> becomes exclusive offsets
    int*   cnt  = hist + NLOC;          // [NLOC]
    int*   sadj = cnt + NLOC;           // [CAP]  local edge ids grouped by dst
    float* sW   = (float*)(sadj + CAP); // 6 x 1024
    float* sb1  = sW + 6144;            // 32
    float* sb2  = sb1 + 32;             // 32
    float* sb3  = sb2 + 32;             // 32

    int t = threadIdx.x;
    int g = blockIdx.x / SPLITS;
    int h = blockIdx.x % SPLITS;
    int nbase = h * NLOC;               // local node base within graph
    int ebase = g * EPG;                // global edge base of this graph

    if (t < NLOC) { hist[t] = 0; cnt[t] = 0; }
    for (int i = t; i < 1024; i += 1024) {
        sW[i]        = Wr1[i]; sW[1024 + i] = Wl1[i];
        sW[2048 + i] = Wr2[i]; sW[3072 + i] = Wl2[i];
        sW[4096 + i] = Wr3[i]; sW[5120 + i] = Wl3[i];
    }
    if (t < 32) { sb1[t] = b1[t]; sb2[t] = b2[t]; sb3[t] = b3[t]; }
    __syncthreads();

    // --- 1) histogram of dst over this block's node range
    const int* dstp = ei + EE + ebase;
    for (int i = t; i < EPG; i += 1024) {
        int dl = __ldg(&dstp[i]) - g * NPG - nbase;
        if ((unsigned)dl < (unsigned)NLOC) atomicAdd(&hist[dl], 1);
    }
    __syncthreads();

    // --- 2) exclusive scan of hist[NLOC] (Hillis-Steele, scratch in sadj)
    {
        int* s0 = sadj;           // [NLOC]
        int* s1 = sadj + NLOC;    // [NLOC]
        if (t < NLOC) s0[t] = hist[t];
        __syncthreads();
        int cur = 0;
        for (int off = 1; off < NLOC; off <<= 1) {
            int* a = cur ? s1 : s0;
            int* b = cur ? s0 : s1;
            if (t < NLOC) b[t] = a[t] + (t >= off ? a[t - off] : 0);
            __syncthreads();
            cur ^= 1;
        }
        int* fin = cur ? s1 : s0;
        int excl = (t < NLOC) ? (t ? fin[t - 1] : 0) : 0;
        __syncthreads();          // done reading scratch
        if (t < NLOC) hist[t] = excl;
    }
    __syncthreads();

    // --- 3) place local edge ids (arbitrary order; sorted later)
    for (int i = t; i < EPG; i += 1024) {
        int dl = __ldg(&dstp[i]) - g * NPG - nbase;
        if ((unsigned)dl < (unsigned)NLOC) {
            int pos = atomicAdd(&cnt[dl], 1);
            sadj[hist[dl] + pos] = i;
        }
    }
    __syncthreads();

    // --- 4) per node: sort eids, aggregate in edge order, score + x3
    int w = t >> 5, lane = t & 31;
    const int* srcp = ei + ebase;
    for (int j = 0; j < NLOC / 32; j++) {
        int nl = w * (NLOC / 32) + j;
        int off = hist[nl];
        int d = cnt[nl];
        int n = g * NPG + nbase + nl;

        float acc = 0.0f;
        if (d > 0 && d <= 32) {
            int v = (lane < d) ? sadj[off + lane] : INT_MAX;
            // 32-lane register bitonic sort (ascending)
#pragma unroll
            for (int k2 = 2; k2 <= 32; k2 <<= 1) {
#pragma unroll
                for (int jj = k2 >> 1; jj >= 1; jj >>= 1) {
                    int other = __shfl_xor_sync(0xffffffffu, v, jj);
                    bool up = ((lane & k2) == 0);
                    bool keepmin = (((lane & jj) == 0) == up);
                    v = keepmin ? min(v, other) : max(v, other);
                }
            }
            int src = (lane < d) ? __ldg(&srcp[v]) : 0;
#pragma unroll
            for (int jj = 0; jj < 32; jj++) {
                if (jj < d) {
                    int sj = __shfl_sync(0xffffffffu, src, jj);
                    acc = __fadd_rn(acc, __ldg(&x[(size_t)sj * DD + lane]));
                }
            }
        } else if (d > 32) {
            // rare generic path: sequential min-extraction from smem
            int cur = -1;
            for (int k = 0; k < d; k++) {
                int m = INT_MAX;
                for (int i = lane; i < d; i += 32) {
                    int e = sadj[off + i];
                    if (e > cur && e < m) m = e;
                }
#pragma unroll
                for (int o = 16; o; o >>= 1)
                    m = min(m, __shfl_xor_sync(0xffffffffu, m, o));
                int sj = __ldg(&srcp[m]);
                acc = __fadd_rn(acc, __ldg(&x[(size_t)sj * DD + lane]));
                cur = m;
            }
        }

        // score + x3 (exact R3 association order), shared xk/ak broadcasts
        float xv = __ldg(&x[(size_t)n * DD + lane]);
        float av = acc;
        float a1 = 0.f, c1 = 0.f, a2 = 0.f, c2 = 0.f, a3 = 0.f, c3 = 0.f;
#pragma unroll
        for (int k = 0; k < 32; k++) {
            float xk = __shfl_sync(0xffffffffu, xv, k);
            float ak = __shfl_sync(0xffffffffu, av, k);
            a1 = __fmaf_rn(xk, sW[k * 32 + lane], a1);
            c1 = __fmaf_rn(ak, sW[1024 + k * 32 + lane], c1);
            a2 = __fmaf_rn(xk, sW[2048 + k * 32 + lane], a2);
            c2 = __fmaf_rn(ak, sW[3072 + k * 32 + lane], c2);
            a3 = __fmaf_rn(xk, sW[4096 + k * 32 + lane], a3);
            c3 = __fmaf_rn(ak, sW[5120 + k * 32 + lane], c3);
        }
        float x2 = __fadd_rn(__fadd_rn(a1, c1), sb1[lane]);
        float y2 = __fadd_rn(__fadd_rn(a2, c2), sb2[lane]);
        g_x3[(size_t)n * DD + lane] = __fadd_rn(__fadd_rn(a3, c3), sb3[lane]);
        float p = __fmul_rn(x2, y2);
        float s = __shfl_sync(0xffffffffu, p, 0);
#pragma unroll
        for (int k = 1; k < 32; k++)
            s = __fadd_rn(s, __shfl_sync(0xffffffffu, p, k));
        if (lane == 0)
            g_score[n] = __fdiv_rn(s, 5.656854249492380195e0f);  // f32 sqrt(32)
    }
}

// ---------------------------------------------------------------------------
// per-graph top-K via bitonic sort of 2048 keys (desc score, asc idx)
__global__ void topk_kernel(float* __restrict__ out) {
    __shared__ unsigned long long sk[NPG];
    int b = blockIdx.x;
    int t = threadIdx.x;     // 1024 threads
    int base = b * NPG;

    for (int i = t; i < NPG; i += 1024) {
        unsigned int bits = __float_as_uint(g_score[base + i]);
        unsigned int m = (bits & 0x80000000u) ? ~bits : (bits | 0x80000000u);
        unsigned int dm = ~m;    // descending order map
        sk[i] = ((unsigned long long)dm << 32) | (unsigned int)i;
    }
    __syncthreads();

    for (int k2 = 2; k2 <= NPG; k2 <<= 1) {
        for (int j = k2 >> 1; j >= 1; j >>= 1) {
            int i  = ((t & ~(j - 1)) << 1) | (t & (j - 1));
            int p2 = i | j;
            bool asc = ((i & k2) == 0);
            unsigned long long a = sk[i], c = sk[p2];
            if ((a > c) == asc) { sk[i] = c; sk[p2] = a; }
            __syncthreads();
        }
    }

    for (int p = t; p < NPG; p += 1024) {
        unsigned long long key = sk[p];
        int idx = (int)(key & 0xFFFFFFFFu);
        int g = base + idx;
        if (p < KK) {
            int r = b * KK + p;
            g_newidx[g] = r;
            g_perm[r]   = g;
            out[OFF_BATCH + r] = (float)b;
            out[OFF_PERM  + r] = (float)g;
            out[OFF_SCORE + r] = g_score[g];
        } else {
            g_newidx[g] = -1;
        }
    }
}

// ---------------------------------------------------------------------------
// filter_adj: 4 edges per thread, vectorized loads/stores.
__global__ void edge_filter_kernel(const int* __restrict__ ei,
                                   const float* __restrict__ ea,
                                   float* __restrict__ out) {
    int e4 = blockIdx.x * blockDim.x + threadIdx.x;  // < EE/4
    int4 sp = __ldg((const int4*)ei + e4);
    int4 dp = __ldg((const int4*)(ei + EE) + e4);
    float4 av = __ldg((const float4*)ea + e4);
    int ns0 = g_newidx[sp.x], ns1 = g_newidx[sp.y];
    int ns2 = g_newidx[sp.z], ns3 = g_newidx[sp.w];
    int nd0 = g_newidx[dp.x], nd1 = g_newidx[dp.y];
    int nd2 = g_newidx[dp.z], nd3 = g_newidx[dp.w];
    bool v0 = (ns0 >= 0) && (nd0 >= 0);
    bool v1 = (ns1 >= 0) && (nd1 >= 0);
    bool v2 = (ns2 >= 0) && (nd2 >= 0);
    bool v3 = (ns3 >= 0) && (nd3 >= 0);
    float4 so = make_float4(v0 ? (float)ns0 : -1.0f, v1 ? (float)ns1 : -1.0f,
                            v2 ? (float)ns2 : -1.0f, v3 ? (float)ns3 : -1.0f);
    float4 dd = make_float4(v0 ? (float)nd0 : -1.0f, v1 ? (float)nd1 : -1.0f,
                            v2 ? (float)nd2 : -1.0f, v3 ? (float)nd3 : -1.0f);
    float4 ao = make_float4(v0 ? av.x : 0.0f, v1 ? av.y : 0.0f,
                            v2 ? av.z : 0.0f, v3 ? av.w : 0.0f);
    ((float4*)(out + OFF_EI))[e4]      = so;
    ((float4*)(out + OFF_EI + EE))[e4] = dd;
    ((float4*)(out + OFF_EA))[e4]      = ao;
}

// ---------------------------------------------------------------------------
// x5 = x[perm] + score[perm] * x3[perm] -- pure coalesced gather now.
__global__ void x5_kernel(const float* __restrict__ x,
                          float* __restrict__ out) {
    int t = blockIdx.x * blockDim.x + threadIdx.x;   // < BK*32
    int i = t >> 5;           // kept-node index
    int lane = t & 31;
    int p = g_perm[i];
    float sc = g_score[p];
    float xv = __ldg(&x[(size_t)p * DD + lane]);
    float x3 = g_x3[(size_t)p * DD + lane];
    out[OFF_X5 + (size_t)t] = __fadd_rn(xv, __fmul_rn(sc, x3));
}

// ---------------------------------------------------------------------------
extern "C" void kernel_launch(void* const* d_in, const int* in_sizes, int n_in,
                              void* d_out, int out_size) {
    const float* x    = (const float*)d_in[0];
    const int*   ei   = (const int*)  d_in[1];
    const float* ea   = (const float*)d_in[2];
    // d_in[3] = batch (unused: batch[perm] == graph id, computed directly)
    const float* Wr1 = (const float*)d_in[4];
    const float* Wl1 = (const float*)d_in[5];
    const float* b1  = (const float*)d_in[6];
    const float* Wr2 = (const float*)d_in[7];
    const float* Wl2 = (const float*)d_in[8];
    const float* b2  = (const float*)d_in[9];
    const float* Wr3 = (const float*)d_in[10];
    const float* Wl3 = (const float*)d_in[11];
    const float* b3  = (const float*)d_in[12];
    float* out = (float*)d_out;

    const int smem_bytes = (NLOC + NLOC + CAP) * 4 + (6144 + 96) * 4;
    cudaFuncSetAttribute(fused_kernel,
                         cudaFuncAttributeMaxDynamicSharedMemorySize, smem_bytes);

    fused_kernel<<<BG * SPLITS, 1024, smem_bytes>>>(x, ei, Wr1, Wl1, b1,
                                                    Wr2, Wl2, b2, Wr3, Wl3, b3);
    topk_kernel<<<BG, 1024>>>(out);
    edge_filter_kernel<<<(EE / 4) / 256, 256>>>(ei, ea, out);
    x5_kernel<<<(BK * 32) / 256, 256>>>(x, out);
}

// round 8
// speedup vs baseline: 1.0785x; 1.0785x over previous
#include <cuda_runtime.h>
#include <cuda_bf16.h>
#include <cstdint>
#include <climits>

// Problem constants
#define BG   64
#define NPG  2048
#define NN   (BG * NPG)      // 131072 nodes
#define EPG  32768
#define EE   (BG * EPG)      // 2097152 edges
#define DD   32
#define KK   1024            // kept per graph
#define BK   (BG * KK)       // 65536 kept total

#define SPLITS 4             // blocks per graph
#define NLOC   (NPG / SPLITS)   // 512 nodes per block
#define CAP    9728          // adjacency capacity per block (mean 8192, +19 sigma)
#define WPAD   36            // padded column stride for transposed weights

// Output layout (flattened f32, reference return order)
#define OFF_X5     ((size_t)0)                       // BK*DD
#define OFF_EI     ((size_t)(BK * DD))               // 2*EE
#define OFF_EA     (OFF_EI + (size_t)(2 * EE))       // EE
#define OFF_BATCH  (OFF_EA + (size_t)EE)             // BK
#define OFF_PERM   (OFF_BATCH + (size_t)BK)          // BK
#define OFF_SCORE  (OFF_PERM + (size_t)BK)           // BK

// Scratch (device globals -- no allocation allowed)
__device__ float g_agg[(size_t)NN * DD];
__device__ float g_score[NN];
__device__ int   g_newidx[NN];
__device__ int   g_perm[BK];

// ---------------------------------------------------------------------------
// Fused: per-block CSR build (smem) + edge-order aggregation + score.
// Block b: graph g = b/SPLITS, node range [h*NLOC,(h+1)*NLOC), h = b%SPLITS.
// 512 threads. GEMV: 2-node register blocking, transposed fp32x4 weights,
// z staged in smem and read as float4 broadcasts. Accumulation order is
// k-sequential per chain -> bit-identical to the R3/R5 passing arithmetic.
__global__ __launch_bounds__(512) void fused_kernel(
    const float* __restrict__ x, const int* __restrict__ ei,
    const float* __restrict__ Wr1, const float* __restrict__ Wl1,
    const float* __restrict__ b1,
    const float* __restrict__ Wr2, const float* __restrict__ Wl2,
    const float* __restrict__ b2) {
    extern __shared__ int smem[];
    int*   hist = smem;                 // [NLOC] -> becomes exclusive offsets
    int*   cnt  = hist + NLOC;          // [NLOC]
    int*   sadj = cnt + NLOC;           // [CAP]
    float* WT   = (float*)(sadj + CAP); // 4 * 32 * WPAD transposed weights
    float* zb   = WT + 4 * 32 * WPAD;   // 16 warps * 128 floats staging
    float* sb1  = zb + 16 * 128;        // 32
    float* sb2  = sb1 + 32;             // 32

    int t = threadIdx.x;
    int g = blockIdx.x / SPLITS;
    int h = blockIdx.x % SPLITS;
    int nbase = h * NLOC;
    int ebase = g * EPG;

    if (t < NLOC) { hist[t] = 0; cnt[t] = 0; }
    // transpose weights: WT[m][j*WPAD + k] = Wm[k*32 + j]
    for (int i = t; i < 1024; i += 512) {
        int k = i >> 5, j = i & 31;
        WT[0 * 32 * WPAD + j * WPAD + k] = Wr1[i];
        WT[1 * 32 * WPAD + j * WPAD + k] = Wl1[i];
        WT[2 * 32 * WPAD + j * WPAD + k] = Wr2[i];
        WT[3 * 32 * WPAD + j * WPAD + k] = Wl2[i];
    }
    if (t < 32) { sb1[t] = b1[t]; sb2[t] = b2[t]; }
    __syncthreads();

    // --- 1) histogram of dst over this block's node range
    const int* dstp = ei + EE + ebase;
    for (int i = t; i < EPG; i += 512) {
        int dl = __ldg(&dstp[i]) - g * NPG - nbase;
        if ((unsigned)dl < (unsigned)NLOC) atomicAdd(&hist[dl], 1);
    }
    __syncthreads();

    // --- 2) exclusive scan of hist[NLOC] (Hillis-Steele, scratch in sadj)
    {
        int* s0 = sadj;
        int* s1 = sadj + NLOC;
        s0[t] = hist[t];
        __syncthreads();
        int cur = 0;
        for (int off = 1; off < NLOC; off <<= 1) {
            int* a = cur ? s1 : s0;
            int* b = cur ? s0 : s1;
            b[t] = a[t] + (t >= off ? a[t - off] : 0);
            __syncthreads();
            cur ^= 1;
        }
        int* fin = cur ? s1 : s0;
        int excl = t ? fin[t - 1] : 0;
        __syncthreads();
        hist[t] = excl;
    }
    __syncthreads();

    // --- 3) place local edge ids (arbitrary order; sorted later)
    for (int i = t; i < EPG; i += 512) {
        int dl = __ldg(&dstp[i]) - g * NPG - nbase;
        if ((unsigned)dl < (unsigned)NLOC) {
            int pos = atomicAdd(&cnt[dl], 1);
            sadj[hist[dl] + pos] = i;
        }
    }
    __syncthreads();

    // --- 4) per node pair: sort eids, aggregate in edge order, score
    int w = t >> 5, lane = t & 31;
    const int* srcp = ei + ebase;
    float* zw = zb + w * 128;
    const float4* wt0 = (const float4*)&WT[0 * 32 * WPAD + lane * WPAD];
    const float4* wt1 = (const float4*)&WT[1 * 32 * WPAD + lane * WPAD];
    const float4* wt2 = (const float4*)&WT[2 * 32 * WPAD + lane * WPAD];
    const float4* wt3 = (const float4*)&WT[3 * 32 * WPAD + lane * WPAD];

    for (int grp = 0; grp < 16; grp++) {
#pragma unroll
        for (int u = 0; u < 2; u++) {
            int nl = w * 32 + grp * 2 + u;
            int off = hist[nl];
            int d = cnt[nl];
            int n = g * NPG + nbase + nl;

            float acc = 0.0f;
            if (d > 0 && d <= 32) {
                int v = (lane < d) ? sadj[off + lane] : INT_MAX;
#pragma unroll
                for (int k2 = 2; k2 <= 32; k2 <<= 1) {
#pragma unroll
                    for (int jj = k2 >> 1; jj >= 1; jj >>= 1) {
                        int other = __shfl_xor_sync(0xffffffffu, v, jj);
                        bool up = ((lane & k2) == 0);
                        bool keepmin = (((lane & jj) == 0) == up);
                        v = keepmin ? min(v, other) : max(v, other);
                    }
                }
                int src = (lane < d) ? __ldg(&srcp[v]) : 0;
#pragma unroll
                for (int jj = 0; jj < 32; jj++) {
                    if (jj < d) {
                        int sj = __shfl_sync(0xffffffffu, src, jj);
                        acc = __fadd_rn(acc, __ldg(&x[(size_t)sj * DD + lane]));
                    }
                }
            } else if (d > 32) {
                int cur = -1;
                for (int k = 0; k < d; k++) {
                    int m = INT_MAX;
                    for (int i = lane; i < d; i += 32) {
                        int e = sadj[off + i];
                        if (e > cur && e < m) m = e;
                    }
#pragma unroll
                    for (int o = 16; o; o >>= 1)
                        m = min(m, __shfl_xor_sync(0xffffffffu, m, o));
                    int sj = __ldg(&srcp[m]);
                    acc = __fadd_rn(acc, __ldg(&x[(size_t)sj * DD + lane]));
                    cur = m;
                }
            }
            int n_ = n;
            float xv = __ldg(&x[(size_t)n_ * DD + lane]);
            g_agg[(size_t)n_ * DD + lane] = acc;
            zw[u * 64 + lane]      = xv;
            zw[u * 64 + 32 + lane] = acc;
        }
        __syncwarp();

        // pair GEMV: weights fetched once per pair, z as float4 broadcasts
        float a1[2] = {0.f, 0.f}, c1[2] = {0.f, 0.f};
        float a2[2] = {0.f, 0.f}, c2[2] = {0.f, 0.f};
#pragma unroll
        for (int k4 = 0; k4 < 8; k4++) {
            float4 wr1 = wt0[k4];
            float4 wl1 = wt1[k4];
            float4 wr2 = wt2[k4];
            float4 wl2 = wt3[k4];
#pragma unroll
            for (int u = 0; u < 2; u++) {
                float4 xk = *(const float4*)&zw[u * 64 + k4 * 4];
                float4 ak = *(const float4*)&zw[u * 64 + 32 + k4 * 4];
                a1[u] = __fmaf_rn(xk.x, wr1.x, a1[u]);
                a1[u] = __fmaf_rn(xk.y, wr1.y, a1[u]);
                a1[u] = __fmaf_rn(xk.z, wr1.z, a1[u]);
                a1[u] = __fmaf_rn(xk.w, wr1.w, a1[u]);
                c1[u] = __fmaf_rn(ak.x, wl1.x, c1[u]);
                c1[u] = __fmaf_rn(ak.y, wl1.y, c1[u]);
                c1[u] = __fmaf_rn(ak.z, wl1.z, c1[u]);
                c1[u] = __fmaf_rn(ak.w, wl1.w, c1[u]);
                a2[u] = __fmaf_rn(xk.x, wr2.x, a2[u]);
                a2[u] = __fmaf_rn(xk.y, wr2.y, a2[u]);
                a2[u] = __fmaf_rn(xk.z, wr2.z, a2[u]);
                a2[u] = __fmaf_rn(xk.w, wr2.w, a2[u]);
                c2[u] = __fmaf_rn(ak.x, wl2.x, c2[u]);
                c2[u] = __fmaf_rn(ak.y, wl2.y, c2[u]);
                c2[u] = __fmaf_rn(ak.z, wl2.z, c2[u]);
                c2[u] = __fmaf_rn(ak.w, wl2.w, c2[u]);
            }
        }
#pragma unroll
        for (int u = 0; u < 2; u++) {
            int n = g * NPG + nbase + w * 32 + grp * 2 + u;
            float x2 = __fadd_rn(__fadd_rn(a1[u], c1[u]), sb1[lane]);
            float y2 = __fadd_rn(__fadd_rn(a2[u], c2[u]), sb2[lane]);
            float p = __fmul_rn(x2, y2);
            float s = __shfl_sync(0xffffffffu, p, 0);
#pragma unroll
            for (int k = 1; k < 32; k++)
                s = __fadd_rn(s, __shfl_sync(0xffffffffu, p, k));
            if (lane == 0)
                g_score[n] = __fdiv_rn(s, 5.656854249492380195e0f);  // f32 sqrt(32)
        }
        __syncwarp();
    }
}

// ---------------------------------------------------------------------------
// per-graph top-K via bitonic sort of 2048 keys (desc score, asc idx)
__global__ void topk_kernel(float* __restrict__ out) {
    __shared__ unsigned long long sk[NPG];
    int b = blockIdx.x;
    int t = threadIdx.x;     // 1024 threads
    int base = b * NPG;

    for (int i = t; i < NPG; i += 1024) {
        unsigned int bits = __float_as_uint(g_score[base + i]);
        unsigned int m = (bits & 0x80000000u) ? ~bits : (bits | 0x80000000u);
        unsigned int dm = ~m;    // descending order map
        sk[i] = ((unsigned long long)dm << 32) | (unsigned int)i;
    }
    __syncthreads();

    for (int k2 = 2; k2 <= NPG; k2 <<= 1) {
        for (int j = k2 >> 1; j >= 1; j >>= 1) {
            int i  = ((t & ~(j - 1)) << 1) | (t & (j - 1));
            int p2 = i | j;
            bool asc = ((i & k2) == 0);
            unsigned long long a = sk[i], c = sk[p2];
            if ((a > c) == asc) { sk[i] = c; sk[p2] = a; }
            __syncthreads();
        }
    }

    for (int p = t; p < NPG; p += 1024) {
        unsigned long long key = sk[p];
        int idx = (int)(key & 0xFFFFFFFFu);
        int g = base + idx;
        if (p < KK) {
            int r = b * KK + p;
            g_newidx[g] = r;
            g_perm[r]   = g;
            out[OFF_BATCH + r] = (float)b;
            out[OFF_PERM  + r] = (float)g;
            out[OFF_SCORE + r] = g_score[g];
        } else {
            g_newidx[g] = -1;
        }
    }
}

// ---------------------------------------------------------------------------
// filter_adj: 4 edges per thread, vectorized loads/stores.
__global__ void edge_filter_kernel(const int* __restrict__ ei,
                                   const float* __restrict__ ea,
                                   float* __restrict__ out) {
    int e4 = blockIdx.x * blockDim.x + threadIdx.x;  // < EE/4
    int4 sp = __ldg((const int4*)ei + e4);
    int4 dp = __ldg((const int4*)(ei + EE) + e4);
    float4 av = __ldg((const float4*)ea + e4);
    int ns0 = g_newidx[sp.x], ns1 = g_newidx[sp.y];
    int ns2 = g_newidx[sp.z], ns3 = g_newidx[sp.w];
    int nd0 = g_newidx[dp.x], nd1 = g_newidx[dp.y];
    int nd2 = g_newidx[dp.z], nd3 = g_newidx[dp.w];
    bool v0 = (ns0 >= 0) && (nd0 >= 0);
    bool v1 = (ns1 >= 0) && (nd1 >= 0);
    bool v2 = (ns2 >= 0) && (nd2 >= 0);
    bool v3 = (ns3 >= 0) && (nd3 >= 0);
    float4 so = make_float4(v0 ? (float)ns0 : -1.0f, v1 ? (float)ns1 : -1.0f,
                            v2 ? (float)ns2 : -1.0f, v3 ? (float)ns3 : -1.0f);
    float4 dd = make_float4(v0 ? (float)nd0 : -1.0f, v1 ? (float)nd1 : -1.0f,
                            v2 ? (float)nd2 : -1.0f, v3 ? (float)nd3 : -1.0f);
    float4 ao = make_float4(v0 ? av.x : 0.0f, v1 ? av.y : 0.0f,
                            v2 ? av.z : 0.0f, v3 ? av.w : 0.0f);
    ((float4*)(out + OFF_EI))[e4]      = so;
    ((float4*)(out + OFF_EI + EE))[e4] = dd;
    ((float4*)(out + OFF_EA))[e4]      = ao;
}

// ---------------------------------------------------------------------------
// x3 + x5 fused, surviving nodes only: warp per node pair, same GEMV scheme.
// x5 = x[p] + score[p] * ((x[p].Wr3 + agg[p].Wl3) + b3)
__global__ __launch_bounds__(512) void x3x5_kernel(
    const float* __restrict__ x,
    const float* __restrict__ Wr3, const float* __restrict__ Wl3,
    const float* __restrict__ b3,
    float* __restrict__ out) {
    __shared__ float WT[2 * 32 * WPAD];
    __shared__ float zb[16 * 128];
    __shared__ float sb3[32];
    int t = threadIdx.x;
    for (int i = t; i < 1024; i += 512) {
        int k = i >> 5, j = i & 31;
        WT[0 * 32 * WPAD + j * WPAD + k] = Wr3[i];
        WT[1 * 32 * WPAD + j * WPAD + k] = Wl3[i];
    }
    if (t < 32) sb3[t] = b3[t];
    __syncthreads();

    int w = t >> 5, lane = t & 31;
    float* zw = zb + w * 128;
    const float4* wt0 = (const float4*)&WT[0 * 32 * WPAD + lane * WPAD];
    const float4* wt1 = (const float4*)&WT[1 * 32 * WPAD + lane * WPAD];

    int i0 = blockIdx.x * 32 + w * 2;    // kept-node pair
    int p0 = g_perm[i0], p1 = g_perm[i0 + 1];
    float xv0 = __ldg(&x[(size_t)p0 * DD + lane]);
    float xv1 = __ldg(&x[(size_t)p1 * DD + lane]);
    zw[lane]       = xv0;
    zw[32 + lane]  = g_agg[(size_t)p0 * DD + lane];
    zw[64 + lane]  = xv1;
    zw[96 + lane]  = g_agg[(size_t)p1 * DD + lane];
    __syncwarp();

    float a[2] = {0.f, 0.f}, c[2] = {0.f, 0.f};
#pragma unroll
    for (int k4 = 0; k4 < 8; k4++) {
        float4 wr = wt0[k4];
        float4 wl = wt1[k4];
#pragma unroll
        for (int u = 0; u < 2; u++) {
            float4 xk = *(const float4*)&zw[u * 64 + k4 * 4];
            float4 ak = *(const float4*)&zw[u * 64 + 32 + k4 * 4];
            a[u] = __fmaf_rn(xk.x, wr.x, a[u]);
            a[u] = __fmaf_rn(xk.y, wr.y, a[u]);
            a[u] = __fmaf_rn(xk.z, wr.z, a[u]);
            a[u] = __fmaf_rn(xk.w, wr.w, a[u]);
            c[u] = __fmaf_rn(ak.x, wl.x, c[u]);
            c[u] = __fmaf_rn(ak.y, wl.y, c[u]);
            c[u] = __fmaf_rn(ak.z, wl.z, c[u]);
            c[u] = __fmaf_rn(ak.w, wl.w, c[u]);
        }
    }
    float sc0 = g_score[p0], sc1 = g_score[p1];
    float x30 = __fadd_rn(__fadd_rn(a[0], c[0]), sb3[lane]);
    float x31 = __fadd_rn(__fadd_rn(a[1], c[1]), sb3[lane]);
    out[OFF_X5 + (size_t)i0 * DD + lane]       = __fadd_rn(xv0, __fmul_rn(sc0, x30));
    out[OFF_X5 + (size_t)(i0 + 1) * DD + lane] = __fadd_rn(xv1, __fmul_rn(sc1, x31));
}

// ---------------------------------------------------------------------------
extern "C" void kernel_launch(void* const* d_in, const int* in_sizes, int n_in,
                              void* d_out, int out_size) {
    const float* x    = (const float*)d_in[0];
    const int*   ei   = (const int*)  d_in[1];
    const float* ea   = (const float*)d_in[2];
    // d_in[3] = batch (unused: batch[perm] == graph id, computed directly)
    const float* Wr1 = (const float*)d_in[4];
    const float* Wl1 = (const float*)d_in[5];
    const float* b1  = (const float*)d_in[6];
    const float* Wr2 = (const float*)d_in[7];
    const float* Wl2 = (const float*)d_in[8];
    const float* b2  = (const float*)d_in[9];
    const float* Wr3 = (const float*)d_in[10];
    const float* Wl3 = (const float*)d_in[11];
    const float* b3  = (const float*)d_in[12];
    float* out = (float*)d_out;

    const int smem_bytes = (NLOC + NLOC + CAP) * 4
                         + (4 * 32 * WPAD + 16 * 128 + 64) * 4;
    cudaFuncSetAttribute(fused_kernel,
                         cudaFuncAttributeMaxDynamicSharedMemorySize, smem_bytes);

    fused_kernel<<<BG * SPLITS, 512, smem_bytes>>>(x, ei, Wr1, Wl1, b1,
                                                   Wr2, Wl2, b2);
    topk_kernel<<<BG, 1024>>>(out);
    edge_filter_kernel<<<(EE / 4) / 256, 256>>>(ei, ea, out);
    x3x5_kernel<<<BK / 32, 512>>>(x, Wr3, Wl3, b3, out);
}

// round 9
// speedup vs baseline: 1.1695x; 1.0843x over previous
#include <cuda_runtime.h>
#include <cuda_bf16.h>
#include <cstdint>
#include <climits>

// Problem constants
#define BG   64
#define NPG  2048
#define NN   (BG * NPG)      // 131072 nodes
#define EPG  32768
#define EE   (BG * EPG)      // 2097152 edges
#define DD   32
#define KK   1024            // kept per graph
#define BK   (BG * KK)       // 65536 kept total

#define SPLITS 4             // blocks per graph
#define NLOC   (NPG / SPLITS)   // 512 nodes per block
#define CAP    9728          // adjacency capacity per block (mean 8192, +17 sigma)
#define WPAD   36            // padded column stride (floats) for transposed weights

// Output layout (flattened f32, reference return order)
#define OFF_X5     ((size_t)0)                       // BK*DD
#define OFF_EI     ((size_t)(BK * DD))               // 2*EE
#define OFF_EA     (OFF_EI + (size_t)(2 * EE))       // EE
#define OFF_BATCH  (OFF_EA + (size_t)EE)             // BK
#define OFF_PERM   (OFF_BATCH + (size_t)BK)          // BK
#define OFF_SCORE  (OFF_PERM + (size_t)BK)           // BK

// Scratch (device globals -- no allocation allowed)
__device__ float g_agg[(size_t)NN * DD];
__device__ float g_score[NN];
__device__ int   g_newidx[NN];
__device__ int   g_perm[BK];

typedef unsigned long long ull;

// packed f32x2 FMA: each 32-bit half is an independent IEEE fma.rn.f32
__device__ __forceinline__ void ffma2(ull& acc, ull w, ull z) {
    asm("fma.rn.f32x2 %0, %1, %2, %3;" : "=l"(acc) : "l"(w), "l"(z), "l"(acc));
}
__device__ __forceinline__ ull pack2(float v) {
    ull r;
    asm("mov.b64 %0, {%1, %2};" : "=l"(r) : "f"(v), "f"(v));
    return r;
}
__device__ __forceinline__ float2 unpack2(ull v) {
    float2 r;
    asm("mov.b64 {%0, %1}, %2;" : "=f"(r.x), "=f"(r.y) : "l"(v));
    return r;
}

// ---------------------------------------------------------------------------
// Fused: per-block CSR build (smem) + edge-order aggregation + score.
// Block b: graph g = b/SPLITS, nodes [h*NLOC,(h+1)*NLOC), h = b%SPLITS.
// 512 threads, warp handles 32 nodes in 8 groups of 4 (FFMA2 pair-packed).
__global__ __launch_bounds__(512, 2) void fused_kernel(
    const float* __restrict__ x, const int* __restrict__ ei,
    const float* __restrict__ Wr1, const float* __restrict__ Wl1,
    const float* __restrict__ b1,
    const float* __restrict__ Wr2, const float* __restrict__ Wl2,
    const float* __restrict__ b2) {
    extern __shared__ int smem[];
    int*            hist = smem;                        // [512]
    int*            cnt  = hist + NLOC;                 // [512]
    unsigned short* sadj = (unsigned short*)(cnt + NLOC); // [CAP] u16 local eids
    float*          WT   = (float*)(sadj + CAP);        // 4 * 32 * WPAD
    float*          zs   = WT + 4 * 32 * WPAD;          // 16 warps * 256 floats
    float*          sb1  = zs + 16 * 256;               // 32
    float*          sb2  = sb1 + 32;                    // 32

    int t = threadIdx.x;
    int g = blockIdx.x / SPLITS;
    int h = blockIdx.x % SPLITS;
    int nbase = h * NLOC;
    int ebase = g * EPG;

    hist[t] = 0; cnt[t] = 0;
    // transpose weights: WT[m][j*WPAD + k] = Wm[k*32 + j]
    for (int i = t; i < 1024; i += 512) {
        int k = i >> 5, j = i & 31;
        WT[(0 * 32 + j) * WPAD + k] = Wr1[i];
        WT[(1 * 32 + j) * WPAD + k] = Wl1[i];
        WT[(2 * 32 + j) * WPAD + k] = Wr2[i];
        WT[(3 * 32 + j) * WPAD + k] = Wl2[i];
    }
    if (t < 32) { sb1[t] = b1[t]; sb2[t] = b2[t]; }
    __syncthreads();

    // --- 1) histogram of dst over this block's node range
    const int* dstp = ei + EE + ebase;
    for (int i = t; i < EPG; i += 512) {
        int dl = __ldg(&dstp[i]) - g * NPG - nbase;
        if ((unsigned)dl < (unsigned)NLOC) atomicAdd(&hist[dl], 1);
    }
    __syncthreads();

    // --- 2) exclusive scan of hist[NLOC] (Hillis-Steele; scratch in zs area)
    {
        int* s0 = (int*)zs;
        int* s1 = s0 + NLOC;
        s0[t] = hist[t];
        __syncthreads();
        int cur = 0;
        for (int off = 1; off < NLOC; off <<= 1) {
            int* a = cur ? s1 : s0;
            int* b = cur ? s0 : s1;
            b[t] = a[t] + (t >= off ? a[t - off] : 0);
            __syncthreads();
            cur ^= 1;
        }
        int* fin = cur ? s1 : s0;
        int excl = t ? fin[t - 1] : 0;
        __syncthreads();
        hist[t] = excl;
    }
    __syncthreads();

    // --- 3) place local edge ids (arbitrary order; sorted later)
    for (int i = t; i < EPG; i += 512) {
        int dl = __ldg(&dstp[i]) - g * NPG - nbase;
        if ((unsigned)dl < (unsigned)NLOC) {
            int pos = atomicAdd(&cnt[dl], 1);
            sadj[hist[dl] + pos] = (unsigned short)i;
        }
    }
    __syncthreads();

    // --- 4) 4-node groups: sort eids, aggregate in edge order, score
    int w = t >> 5, lane = t & 31;
    const int* srcp = ei + ebase;
    float* zsw = zs + w * 256;   // [inp(2)][k(32)][u(4)]

    for (int grp = 0; grp < 8; grp++) {
#pragma unroll
        for (int u = 0; u < 4; u++) {
            int nl = w * 32 + grp * 4 + u;
            int off = hist[nl];
            int d = cnt[nl];
            int n = g * NPG + nbase + nl;

            float acc = 0.0f;
            if (d > 0 && d <= 32) {
                int v = (lane < d) ? (int)sadj[off + lane] : INT_MAX;
#pragma unroll
                for (int k2 = 2; k2 <= 32; k2 <<= 1) {
#pragma unroll
                    for (int jj = k2 >> 1; jj >= 1; jj >>= 1) {
                        int other = __shfl_xor_sync(0xffffffffu, v, jj);
                        bool up = ((lane & k2) == 0);
                        bool keepmin = (((lane & jj) == 0) == up);
                        v = keepmin ? min(v, other) : max(v, other);
                    }
                }
                int src = (lane < d) ? __ldg(&srcp[v]) : 0;
#pragma unroll
                for (int b8 = 0; b8 < 32; b8 += 8) {
                    if (b8 < d) {
#pragma unroll
                        for (int j2 = 0; j2 < 8; j2++) {
                            int jj = b8 + j2;
                            if (jj < d) {
                                int sj = __shfl_sync(0xffffffffu, src, jj);
                                acc = __fadd_rn(acc, __ldg(&x[(size_t)sj * DD + lane]));
                            }
                        }
                    }
                }
            } else if (d > 32) {
                int cur = -1;
                for (int k = 0; k < d; k++) {
                    int m = INT_MAX;
                    for (int i = lane; i < d; i += 32) {
                        int e = (int)sadj[off + i];
                        if (e > cur && e < m) m = e;
                    }
#pragma unroll
                    for (int o = 16; o; o >>= 1)
                        m = min(m, __shfl_xor_sync(0xffffffffu, m, o));
                    int sj = __ldg(&srcp[m]);
                    acc = __fadd_rn(acc, __ldg(&x[(size_t)sj * DD + lane]));
                    cur = m;
                }
            }
            g_agg[(size_t)n * DD + lane] = acc;
            float xv = __ldg(&x[(size_t)n * DD + lane]);
            zsw[lane * 4 + u]       = xv;
            zsw[128 + lane * 4 + u] = acc;
        }
        __syncwarp();

        // GEMV: 4 nodes as 2 packed pairs, weights loaded once per group
        ull a1[2] = {0, 0}, c1[2] = {0, 0}, a2[2] = {0, 0}, c2[2] = {0, 0};
#pragma unroll
        for (int k4 = 0; k4 < 8; k4++) {
            float4 wr1 = *(const float4*)&WT[(0 * 32 + lane) * WPAD + k4 * 4];
            float4 wl1 = *(const float4*)&WT[(1 * 32 + lane) * WPAD + k4 * 4];
            float4 wr2 = *(const float4*)&WT[(2 * 32 + lane) * WPAD + k4 * 4];
            float4 wl2 = *(const float4*)&WT[(3 * 32 + lane) * WPAD + k4 * 4];
#define GEMV_STEP(KK, C)                                                     \
            {                                                                \
                int k = k4 * 4 + KK;                                         \
                ulonglong2 zx = *(const ulonglong2*)&zsw[k * 4];             \
                ulonglong2 za = *(const ulonglong2*)&zsw[128 + k * 4];       \
                ull wp;                                                      \
                wp = pack2(wr1.C); ffma2(a1[0], wp, zx.x); ffma2(a1[1], wp, zx.y); \
                wp = pack2(wl1.C); ffma2(c1[0], wp, za.x); ffma2(c1[1], wp, za.y); \
                wp = pack2(wr2.C); ffma2(a2[0], wp, zx.x); ffma2(a2[1], wp, zx.y); \
                wp = pack2(wl2.C); ffma2(c2[0], wp, za.x); ffma2(c2[1], wp, za.y); \
            }
            GEMV_STEP(0, x) GEMV_STEP(1, y) GEMV_STEP(2, z) GEMV_STEP(3, w)
#undef GEMV_STEP
        }
        __syncwarp();

        // epilogue: p = x2*y2 per (node, lane=j) staged for transpose reduce
#pragma unroll
        for (int pp = 0; pp < 2; pp++) {
            float2 A1 = unpack2(a1[pp]), C1 = unpack2(c1[pp]);
            float2 A2 = unpack2(a2[pp]), C2 = unpack2(c2[pp]);
            float x2l = __fadd_rn(__fadd_rn(A1.x, C1.x), sb1[lane]);
            float y2l = __fadd_rn(__fadd_rn(A2.x, C2.x), sb2[lane]);
            zsw[lane * 4 + pp * 2 + 0] = __fmul_rn(x2l, y2l);
            float x2h = __fadd_rn(__fadd_rn(A1.y, C1.y), sb1[lane]);
            float y2h = __fadd_rn(__fadd_rn(A2.y, C2.y), sb2[lane]);
            zsw[lane * 4 + pp * 2 + 1] = __fmul_rn(x2h, y2h);
        }
        __syncwarp();
        if (lane < 4) {
            // left-fold j = 0..31 (reference reduce order)
            float s = zsw[lane];
#pragma unroll
            for (int j = 1; j < 32; j++)
                s = __fadd_rn(s, zsw[j * 4 + lane]);
            int n = g * NPG + nbase + w * 32 + grp * 4 + lane;
            g_score[n] = __fdiv_rn(s, 5.656854249492380195e0f);  // f32 sqrt(32)
        }
        __syncwarp();
    }
}

// ---------------------------------------------------------------------------
// per-graph top-K via bitonic sort of 2048 keys (desc score, asc idx)
__global__ void topk_kernel(float* __restrict__ out) {
    __shared__ unsigned long long sk[NPG];
    int b = blockIdx.x;
    int t = threadIdx.x;     // 1024 threads
    int base = b * NPG;

    for (int i = t; i < NPG; i += 1024) {
        unsigned int bits = __float_as_uint(g_score[base + i]);
        unsigned int m = (bits & 0x80000000u) ? ~bits : (bits | 0x80000000u);
        unsigned int dm = ~m;    // descending order map
        sk[i] = ((unsigned long long)dm << 32) | (unsigned int)i;
    }
    __syncthreads();

    for (int k2 = 2; k2 <= NPG; k2 <<= 1) {
        for (int j = k2 >> 1; j >= 1; j >>= 1) {
            int i  = ((t & ~(j - 1)) << 1) | (t & (j - 1));
            int p2 = i | j;
            bool asc = ((i & k2) == 0);
            unsigned long long a = sk[i], c = sk[p2];
            if ((a > c) == asc) { sk[i] = c; sk[p2] = a; }
            __syncthreads();
        }
    }

    for (int p = t; p < NPG; p += 1024) {
        unsigned long long key = sk[p];
        int idx = (int)(key & 0xFFFFFFFFu);
        int g = base + idx;
        if (p < KK) {
            int r = b * KK + p;
            g_newidx[g] = r;
            g_perm[r]   = g;
            out[OFF_BATCH + r] = (float)b;
            out[OFF_PERM  + r] = (float)g;
            out[OFF_SCORE + r] = g_score[g];
        } else {
            g_newidx[g] = -1;
        }
    }
}

// ---------------------------------------------------------------------------
// filter_adj: 4 edges per thread, vectorized loads/stores.
__global__ void edge_filter_kernel(const int* __restrict__ ei,
                                   const float* __restrict__ ea,
                                   float* __restrict__ out) {
    int e4 = blockIdx.x * blockDim.x + threadIdx.x;  // < EE/4
    int4 sp = __ldg((const int4*)ei + e4);
    int4 dp = __ldg((const int4*)(ei + EE) + e4);
    float4 av = __ldg((const float4*)ea + e4);
    int ns0 = g_newidx[sp.x], ns1 = g_newidx[sp.y];
    int ns2 = g_newidx[sp.z], ns3 = g_newidx[sp.w];
    int nd0 = g_newidx[dp.x], nd1 = g_newidx[dp.y];
    int nd2 = g_newidx[dp.z], nd3 = g_newidx[dp.w];
    bool v0 = (ns0 >= 0) && (nd0 >= 0);
    bool v1 = (ns1 >= 0) && (nd1 >= 0);
    bool v2 = (ns2 >= 0) && (nd2 >= 0);
    bool v3 = (ns3 >= 0) && (nd3 >= 0);
    float4 so = make_float4(v0 ? (float)ns0 : -1.0f, v1 ? (float)ns1 : -1.0f,
                            v2 ? (float)ns2 : -1.0f, v3 ? (float)ns3 : -1.0f);
    float4 dd = make_float4(v0 ? (float)nd0 : -1.0f, v1 ? (float)nd1 : -1.0f,
                            v2 ? (float)nd2 : -1.0f, v3 ? (float)nd3 : -1.0f);
    float4 ao = make_float4(v0 ? av.x : 0.0f, v1 ? av.y : 0.0f,
                            v2 ? av.z : 0.0f, v3 ? av.w : 0.0f);
    ((float4*)(out + OFF_EI))[e4]      = so;
    ((float4*)(out + OFF_EI + EE))[e4] = dd;
    ((float4*)(out + OFF_EA))[e4]      = ao;
}

// ---------------------------------------------------------------------------
// x3 + x5 fused, surviving nodes only: warp per 4 kept nodes, FFMA2 pairs.
// x5 = x[p] + score[p] * ((x[p].Wr3 + agg[p].Wl3) + b3)
__global__ __launch_bounds__(256, 5) void x3x5_kernel(
    const float* __restrict__ x,
    const float* __restrict__ Wr3, const float* __restrict__ Wl3,
    const float* __restrict__ b3,
    float* __restrict__ out) {
    __shared__ float WT[2 * 32 * WPAD];
    __shared__ float zs[8 * 256];
    __shared__ float sb3[32];
    int t = threadIdx.x;
    for (int i = t; i < 1024; i += 256) {
        int k = i >> 5, j = i & 31;
        WT[(0 * 32 + j) * WPAD + k] = Wr3[i];
        WT[(1 * 32 + j) * WPAD + k] = Wl3[i];
    }
    if (t < 32) sb3[t] = b3[t];
    __syncthreads();

    int w = t >> 5, lane = t & 31;
    float* zsw = zs + w * 256;

    int i0 = blockIdx.x * 32 + w * 4;    // 4 kept nodes per warp
    float xv[4], sc[4];
#pragma unroll
    for (int u = 0; u < 4; u++) {
        int p = g_perm[i0 + u];
        sc[u] = g_score[p];
        xv[u] = __ldg(&x[(size_t)p * DD + lane]);
        float av = g_agg[(size_t)p * DD + lane];
        zsw[lane * 4 + u]       = xv[u];
        zsw[128 + lane * 4 + u] = av;
    }
    __syncwarp();

    ull a[2] = {0, 0}, c[2] = {0, 0};
#pragma unroll
    for (int k4 = 0; k4 < 8; k4++) {
        float4 wr = *(const float4*)&WT[(0 * 32 + lane) * WPAD + k4 * 4];
        float4 wl = *(const float4*)&WT[(1 * 32 + lane) * WPAD + k4 * 4];
#define X3_STEP(KK, C)                                                       \
        {                                                                    \
            int k = k4 * 4 + KK;                                             \
            ulonglong2 zx = *(const ulonglong2*)&zsw[k * 4];                 \
            ulonglong2 za = *(const ulonglong2*)&zsw[128 + k * 4];           \
            ull wp;                                                          \
            wp = pack2(wr.C); ffma2(a[0], wp, zx.x); ffma2(a[1], wp, zx.y);  \
            wp = pack2(wl.C); ffma2(c[0], wp, za.x); ffma2(c[1], wp, za.y);  \
        }
        X3_STEP(0, x) X3_STEP(1, y) X3_STEP(2, z) X3_STEP(3, w)
#undef X3_STEP
    }

#pragma unroll
    for (int pp = 0; pp < 2; pp++) {
        float2 A = unpack2(a[pp]), C = unpack2(c[pp]);
        float x3l = __fadd_rn(__fadd_rn(A.x, C.x), sb3[lane]);
        float x3h = __fadd_rn(__fadd_rn(A.y, C.y), sb3[lane]);
        int ul = pp * 2, uh = pp * 2 + 1;
        out[OFF_X5 + (size_t)(i0 + ul) * DD + lane] =
            __fadd_rn(xv[ul], __fmul_rn(sc[ul], x3l));
        out[OFF_X5 + (size_t)(i0 + uh) * DD + lane] =
            __fadd_rn(xv[uh], __fmul_rn(sc[uh], x3h));
    }
}

// ---------------------------------------------------------------------------
extern "C" void kernel_launch(void* const* d_in, const int* in_sizes, int n_in,
                              void* d_out, int out_size) {
    const float* x    = (const float*)d_in[0];
    const int*   ei   = (const int*)  d_in[1];
    const float* ea   = (const float*)d_in[2];
    // d_in[3] = batch (unused: batch[perm] == graph id, computed directly)
    const float* Wr1 = (const float*)d_in[4];
    const float* Wl1 = (const float*)d_in[5];
    const float* b1  = (const float*)d_in[6];
    const float* Wr2 = (const float*)d_in[7];
    const float* Wl2 = (const float*)d_in[8];
    const float* b2  = (const float*)d_in[9];
    const float* Wr3 = (const float*)d_in[10];
    const float* Wl3 = (const float*)d_in[11];
    const float* b3  = (const float*)d_in[12];
    float* out = (float*)d_out;

    const int smem_bytes = NLOC * 4 * 2          // hist + cnt
                         + CAP * 2               // sadj (u16)
                         + 4 * 32 * WPAD * 4     // WT
                         + 16 * 256 * 4          // zs
                         + 64 * 4;               // biases
    cudaFuncSetAttribute(fused_kernel,
                         cudaFuncAttributeMaxDynamicSharedMemorySize, smem_bytes);

    fused_kernel<<<BG * SPLITS, 512, smem_bytes>>>(x, ei, Wr1, Wl1, b1,
                                                   Wr2, Wl2, b2);
    topk_kernel<<<BG, 1024>>>(out);
    edge_filter_kernel<<<(EE / 4) / 256, 256>>>(ei, ea, out);
    x3x5_kernel<<<BK / 32, 256>>>(x, Wr3, Wl3, b3, out);
}

// round 10
// speedup vs baseline: 1.4410x; 1.2322x over previous
#include <cuda_runtime.h>
#include <cuda_bf16.h>
#include <cstdint>
#include <climits>

// Problem constants
#define BG   64
#define NPG  2048
#define NN   (BG * NPG)      // 131072 nodes
#define EPG  32768
#define EE   (BG * EPG)      // 2097152 edges
#define DD   32
#define KK   1024            // kept per graph
#define BK   (BG * KK)       // 65536 kept total

#define SPLITS 8             // blocks per graph
#define NLOC   (NPG / SPLITS)   // 256 nodes per block
#define CAP    5120          // adjacency capacity per block (mean 4096, +17 sigma)
#define WPAD   36            // padded column stride (floats) for transposed weights
#define NW     8             // warps per fused block

// Output layout (flattened f32, reference return order)
#define OFF_X5     ((size_t)0)                       // BK*DD
#define OFF_EI     ((size_t)(BK * DD))               // 2*EE
#define OFF_EA     (OFF_EI + (size_t)(2 * EE))       // EE
#define OFF_BATCH  (OFF_EA + (size_t)EE)             // BK
#define OFF_PERM   (OFF_BATCH + (size_t)BK)          // BK
#define OFF_SCORE  (OFF_PERM + (size_t)BK)           // BK

// Scratch (device globals -- no allocation allowed)
__device__ float g_agg[(size_t)NN * DD];
__device__ float g_score[NN];
__device__ int   g_newidx[NN];
__device__ int   g_perm[BK];

typedef unsigned long long ull;

// packed f32x2 FMA: each 32-bit half is an independent IEEE fma.rn.f32
__device__ __forceinline__ void ffma2(ull& acc, ull w, ull z) {
    asm("fma.rn.f32x2 %0, %1, %2, %3;" : "=l"(acc) : "l"(w), "l"(z), "l"(acc));
}
__device__ __forceinline__ ull pack2(float v) {
    ull r;
    asm("mov.b64 %0, {%1, %2};" : "=l"(r) : "f"(v), "f"(v));
    return r;
}
__device__ __forceinline__ float2 unpack2(ull v) {
    float2 r;
    asm("mov.b64 {%0, %1}, %2;" : "=f"(r.x), "=f"(r.y) : "l"(v));
    return r;
}

// ---------------------------------------------------------------------------
// Fused: per-block CSR build (smem) + edge-order aggregation + score.
// Block b: graph g = b/SPLITS, nodes [h*NLOC,(h+1)*NLOC), h = b%SPLITS.
// 256 threads (8 warps); warp handles 32 nodes in 8 groups of 4.
__global__ __launch_bounds__(256, 5) void fused_kernel(
    const float* __restrict__ x, const int* __restrict__ ei,
    const float* __restrict__ Wr1, const float* __restrict__ Wl1,
    const float* __restrict__ b1,
    const float* __restrict__ Wr2, const float* __restrict__ Wl2,
    const float* __restrict__ b2) {
    extern __shared__ int smem[];
    int*            hist  = smem;                          // [NLOC]
    int*            cnt   = hist + NLOC;                   // [NLOC]
    unsigned short* sadj  = (unsigned short*)(cnt + NLOC); // [CAP] u16 local eids
    float*          WT    = (float*)(sadj + CAP);          // 4 * 32 * WPAD
    float*          zs    = WT + 4 * 32 * WPAD;            // NW warps * 256
    int*            snode = (int*)(zs + NW * 256);         // NW warps * 32
    float*          sb1   = (float*)(snode + NW * 32);     // 32
    float*          sb2   = sb1 + 32;                      // 32

    int t = threadIdx.x;
    int g = blockIdx.x / SPLITS;
    int h = blockIdx.x % SPLITS;
    int nbase = h * NLOC;
    int ebase = g * EPG;

    hist[t] = 0; cnt[t] = 0;
    // transpose weights: WT[m][j*WPAD + k] = Wm[k*32 + j]
    for (int i = t; i < 1024; i += 256) {
        int k = i >> 5, j = i & 31;
        WT[(0 * 32 + j) * WPAD + k] = Wr1[i];
        WT[(1 * 32 + j) * WPAD + k] = Wl1[i];
        WT[(2 * 32 + j) * WPAD + k] = Wr2[i];
        WT[(3 * 32 + j) * WPAD + k] = Wl2[i];
    }
    if (t < 32) { sb1[t] = b1[t]; sb2[t] = b2[t]; }
    __syncthreads();

    // --- 1) histogram of dst over this block's node range
    const int* dstp = ei + EE + ebase;
    for (int i = t; i < EPG; i += 256) {
        int dl = __ldg(&dstp[i]) - g * NPG - nbase;
        if ((unsigned)dl < (unsigned)NLOC) atomicAdd(&hist[dl], 1);
    }
    __syncthreads();

    // --- 2) exclusive scan of hist[NLOC] (Hillis-Steele; scratch in zs area)
    {
        int* s0 = (int*)zs;
        int* s1 = s0 + NLOC;
        s0[t] = hist[t];
        __syncthreads();
        int cur = 0;
        for (int off = 1; off < NLOC; off <<= 1) {
            int* a = cur ? s1 : s0;
            int* b = cur ? s0 : s1;
            b[t] = a[t] + (t >= off ? a[t - off] : 0);
            __syncthreads();
            cur ^= 1;
        }
        int* fin = cur ? s1 : s0;
        int excl = t ? fin[t - 1] : 0;
        __syncthreads();
        hist[t] = excl;
    }
    __syncthreads();

    // --- 3) place local edge ids (arbitrary order; rank-permuted later)
    for (int i = t; i < EPG; i += 256) {
        int dl = __ldg(&dstp[i]) - g * NPG - nbase;
        if ((unsigned)dl < (unsigned)NLOC) {
            int pos = atomicAdd(&cnt[dl], 1);
            sadj[hist[dl] + pos] = (unsigned short)i;
        }
    }
    __syncthreads();

    // --- 4) 4-node groups: rank-order srcs, aggregate in edge order, score
    int w = t >> 5, lane = t & 31;
    const int* srcp = ei + ebase;
    float* zsw = zs + w * 256;    // [inp(2)][k(32)][u(4)]
    int*   sn  = snode + w * 32;

    for (int grp = 0; grp < 8; grp++) {
#pragma unroll
        for (int u = 0; u < 4; u++) {
            int nl = w * 32 + grp * 4 + u;
            int off = hist[nl];
            int d = cnt[nl];
            int n = g * NPG + nbase + nl;

            float acc = 0.0f;
            if (d > 0 && d <= 32) {
                int eid = (lane < d) ? (int)sadj[off + lane] : INT_MAX;
                // rank = #(smaller eids); eids unique -> exact edge order
                int rank = 0;
#pragma unroll
                for (int j = 0; j < 32; j++)
                    rank += (int)(__shfl_sync(0xffffffffu, eid, j) < eid);
                int src = (lane < d) ? __ldg(&srcp[eid]) : 0;
                if (lane < d) sn[rank] = src;
                __syncwarp();
                // edge-order sequential adds; loads prefetched in batches of 8
                for (int b8 = 0; b8 < d; b8 += 8) {
                    float v[8];
#pragma unroll
                    for (int j = 0; j < 8; j++) {
                        v[j] = 0.0f;
                        if (b8 + j < d) {
                            int sj = sn[b8 + j];
                            v[j] = __ldg(&x[(size_t)sj * DD + lane]);
                        }
                    }
#pragma unroll
                    for (int j = 0; j < 8; j++)
                        if (b8 + j < d) acc = __fadd_rn(acc, v[j]);
                }
                __syncwarp();
            } else if (d > 32) {
                // rare fallback: sequential min-extraction
                int cur = -1;
                for (int k = 0; k < d; k++) {
                    int m = INT_MAX;
                    for (int i = lane; i < d; i += 32) {
                        int e = (int)sadj[off + i];
                        if (e > cur && e < m) m = e;
                    }
#pragma unroll
                    for (int o = 16; o; o >>= 1)
                        m = min(m, __shfl_xor_sync(0xffffffffu, m, o));
                    int sj = __ldg(&srcp[m]);
                    acc = __fadd_rn(acc, __ldg(&x[(size_t)sj * DD + lane]));
                    cur = m;
                }
            }
            g_agg[(size_t)n * DD + lane] = acc;
            float xv = __ldg(&x[(size_t)n * DD + lane]);
            zsw[lane * 4 + u]       = xv;
            zsw[128 + lane * 4 + u] = acc;
        }
        __syncwarp();

        // GEMV: 4 nodes as 2 packed pairs, weights loaded once per group
        ull a1[2] = {0, 0}, c1[2] = {0, 0}, a2[2] = {0, 0}, c2[2] = {0, 0};
#pragma unroll
        for (int k4 = 0; k4 < 8; k4++) {
            float4 wr1 = *(const float4*)&WT[(0 * 32 + lane) * WPAD + k4 * 4];
            float4 wl1 = *(const float4*)&WT[(1 * 32 + lane) * WPAD + k4 * 4];
            float4 wr2 = *(const float4*)&WT[(2 * 32 + lane) * WPAD + k4 * 4];
            float4 wl2 = *(const float4*)&WT[(3 * 32 + lane) * WPAD + k4 * 4];
#define GEMV_STEP(KK, C)                                                     \
            {                                                                \
                int k = k4 * 4 + KK;                                         \
                ulonglong2 zx = *(const ulonglong2*)&zsw[k * 4];             \
                ulonglong2 za = *(const ulonglong2*)&zsw[128 + k * 4];       \
                ull wp;                                                      \
                wp = pack2(wr1.C); ffma2(a1[0], wp, zx.x); ffma2(a1[1], wp, zx.y); \
                wp = pack2(wl1.C); ffma2(c1[0], wp, za.x); ffma2(c1[1], wp, za.y); \
                wp = pack2(wr2.C); ffma2(a2[0], wp, zx.x); ffma2(a2[1], wp, zx.y); \
                wp = pack2(wl2.C); ffma2(c2[0], wp, za.x); ffma2(c2[1], wp, za.y); \
            }
            GEMV_STEP(0, x) GEMV_STEP(1, y) GEMV_STEP(2, z) GEMV_STEP(3, w)
#undef GEMV_STEP
        }
        __syncwarp();

        // epilogue: p = x2*y2 per (node, lane=j) staged for transpose reduce
#pragma unroll
        for (int pp = 0; pp < 2; pp++) {
            float2 A1 = unpack2(a1[pp]), C1 = unpack2(c1[pp]);
            float2 A2 = unpack2(a2[pp]), C2 = unpack2(c2[pp]);
            float x2l = __fadd_rn(__fadd_rn(A1.x, C1.x), sb1[lane]);
            float y2l = __fadd_rn(__fadd_rn(A2.x, C2.x), sb2[lane]);
            zsw[lane * 4 + pp * 2 + 0] = __fmul_rn(x2l, y2l);
            float x2h = __fadd_rn(__fadd_rn(A1.y, C1.y), sb1[lane]);
            float y2h = __fadd_rn(__fadd_rn(A2.y, C2.y), sb2[lane]);
            zsw[lane * 4 + pp * 2 + 1] = __fmul_rn(x2h, y2h);
        }
        __syncwarp();
        if (lane < 4) {
            // left-fold j = 0..31 (reference reduce order)
            float s = zsw[lane];
#pragma unroll
            for (int j = 1; j < 32; j++)
                s = __fadd_rn(s, zsw[j * 4 + lane]);
            int n = g * NPG + nbase + w * 32 + grp * 4 + lane;
            g_score[n] = __fdiv_rn(s, 5.656854249492380195e0f);  // f32 sqrt(32)
        }
        __syncwarp();
    }
}

// ---------------------------------------------------------------------------
// per-graph top-K via bitonic sort of 2048 keys (desc score, asc idx)
__global__ void topk_kernel(float* __restrict__ out) {
    __shared__ unsigned long long sk[NPG];
    int b = blockIdx.x;
    int t = threadIdx.x;     // 1024 threads
    int base = b * NPG;

    for (int i = t; i < NPG; i += 1024) {
        unsigned int bits = __float_as_uint(g_score[base + i]);
        unsigned int m = (bits & 0x80000000u) ? ~bits : (bits | 0x80000000u);
        unsigned int dm = ~m;    // descending order map
        sk[i] = ((unsigned long long)dm << 32) | (unsigned int)i;
    }
    __syncthreads();

    for (int k2 = 2; k2 <= NPG; k2 <<= 1) {
        for (int j = k2 >> 1; j >= 1; j >>= 1) {
            int i  = ((t & ~(j - 1)) << 1) | (t & (j - 1));
            int p2 = i | j;
            bool asc = ((i & k2) == 0);
            unsigned long long a = sk[i], c = sk[p2];
            if ((a > c) == asc) { sk[i] = c; sk[p2] = a; }
            __syncthreads();
        }
    }

    for (int p = t; p < NPG; p += 1024) {
        unsigned long long key = sk[p];
        int idx = (int)(key & 0xFFFFFFFFu);
        int g = base + idx;
        if (p < KK) {
            int r = b * KK + p;
            g_newidx[g] = r;
            g_perm[r]   = g;
            out[OFF_BATCH + r] = (float)b;
            out[OFF_PERM  + r] = (float)g;
            out[OFF_SCORE + r] = g_score[g];
        } else {
            g_newidx[g] = -1;
        }
    }
}

// ---------------------------------------------------------------------------
// filter_adj: 4 edges per thread; streaming stores (write-once output).
__global__ void edge_filter_kernel(const int* __restrict__ ei,
                                   const float* __restrict__ ea,
                                   float* __restrict__ out) {
    int e4 = blockIdx.x * blockDim.x + threadIdx.x;  // < EE/4
    int4 sp = __ldg((const int4*)ei + e4);
    int4 dp = __ldg((const int4*)(ei + EE) + e4);
    float4 av = __ldg((const float4*)ea + e4);
    int ns0 = g_newidx[sp.x], ns1 = g_newidx[sp.y];
    int ns2 = g_newidx[sp.z], ns3 = g_newidx[sp.w];
    int nd0 = g_newidx[dp.x], nd1 = g_newidx[dp.y];
    int nd2 = g_newidx[dp.z], nd3 = g_newidx[dp.w];
    bool v0 = (ns0 >= 0) && (nd0 >= 0);
    bool v1 = (ns1 >= 0) && (nd1 >= 0);
    bool v2 = (ns2 >= 0) && (nd2 >= 0);
    bool v3 = (ns3 >= 0) && (nd3 >= 0);
    float4 so = make_float4(v0 ? (float)ns0 : -1.0f, v1 ? (float)ns1 : -1.0f,
                            v2 ? (float)ns2 : -1.0f, v3 ? (float)ns3 : -1.0f);
    float4 dd = make_float4(v0 ? (float)nd0 : -1.0f, v1 ? (float)nd1 : -1.0f,
                            v2 ? (float)nd2 : -1.0f, v3 ? (float)nd3 : -1.0f);
    float4 ao = make_float4(v0 ? av.x : 0.0f, v1 ? av.y : 0.0f,
                            v2 ? av.z : 0.0f, v3 ? av.w : 0.0f);
    __stcs(&((float4*)(out + OFF_EI))[e4], so);
    __stcs(&((float4*)(out + OFF_EI + EE))[e4], dd);
    __stcs(&((float4*)(out + OFF_EA))[e4], ao);
}

// ---------------------------------------------------------------------------
// x3 + x5 fused, surviving nodes only: warp per 4 kept nodes, FFMA2 pairs.
// x5 = x[p] + score[p] * ((x[p].Wr3 + agg[p].Wl3) + b3)
__global__ __launch_bounds__(256, 5) void x3x5_kernel(
    const float* __restrict__ x,
    const float* __restrict__ Wr3, const float* __restrict__ Wl3,
    const float* __restrict__ b3,
    float* __restrict__ out) {
    __shared__ float WT[2 * 32 * WPAD];
    __shared__ float zs[8 * 256];
    __shared__ float sb3[32];
    int t = threadIdx.x;
    for (int i = t; i < 1024; i += 256) {
        int k = i >> 5, j = i & 31;
        WT[(0 * 32 + j) * WPAD + k] = Wr3[i];
        WT[(1 * 32 + j) * WPAD + k] = Wl3[i];
    }
    if (t < 32) sb3[t] = b3[t];
    __syncthreads();

    int w = t >> 5, lane = t & 31;
    float* zsw = zs + w * 256;

    int i0 = blockIdx.x * 32 + w * 4;    // 4 kept nodes per warp
    float xv[4], sc[4];
#pragma unroll
    for (int u = 0; u < 4; u++) {
        int p = g_perm[i0 + u];
        sc[u] = g_score[p];
        xv[u] = __ldg(&x[(size_t)p * DD + lane]);
        float av = g_agg[(size_t)p * DD + lane];
        zsw[lane * 4 + u]       = xv[u];
        zsw[128 + lane * 4 + u] = av;
    }
    __syncwarp();

    ull a[2] = {0, 0}, c[2] = {0, 0};
#pragma unroll
    for (int k4 = 0; k4 < 8; k4++) {
        float4 wr = *(const float4*)&WT[(0 * 32 + lane) * WPAD + k4 * 4];
        float4 wl = *(const float4*)&WT[(1 * 32 + lane) * WPAD + k4 * 4];
#define X3_STEP(KK, C)                                                       \
        {                                                                    \
            int k = k4 * 4 + KK;                                             \
            ulonglong2 zx = *(const ulonglong2*)&zsw[k * 4];                 \
            ulonglong2 za = *(const ulonglong2*)&zsw[128 + k * 4];           \
            ull wp;                                                          \
            wp = pack2(wr.C); ffma2(a[0], wp, zx.x); ffma2(a[1], wp, zx.y);  \
            wp = pack2(wl.C); ffma2(c[0], wp, za.x); ffma2(c[1], wp, za.y);  \
        }
        X3_STEP(0, x) X3_STEP(1, y) X3_STEP(2, z) X3_STEP(3, w)
#undef X3_STEP
    }

#pragma unroll
    for (int pp = 0; pp < 2; pp++) {
        float2 A = unpack2(a[pp]), C = unpack2(c[pp]);
        float x3l = __fadd_rn(__fadd_rn(A.x, C.x), sb3[lane]);
        float x3h = __fadd_rn(__fadd_rn(A.y, C.y), sb3[lane]);
        int ul = pp * 2, uh = pp * 2 + 1;
        __stcs(&out[OFF_X5 + (size_t)(i0 + ul) * DD + lane],
               __fadd_rn(xv[ul], __fmul_rn(sc[ul], x3l)));
        __stcs(&out[OFF_X5 + (size_t)(i0 + uh) * DD + lane],
               __fadd_rn(xv[uh], __fmul_rn(sc[uh], x3h)));
    }
}

// ---------------------------------------------------------------------------
extern "C" void kernel_launch(void* const* d_in, const int* in_sizes, int n_in,
                              void* d_out, int out_size) {
    const float* x    = (const float*)d_in[0];
    const int*   ei   = (const int*)  d_in[1];
    const float* ea   = (const float*)d_in[2];
    // d_in[3] = batch (unused: batch[perm] == graph id, computed directly)
    const float* Wr1 = (const float*)d_in[4];
    const float* Wl1 = (const float*)d_in[5];
    const float* b1  = (const float*)d_in[6];
    const float* Wr2 = (const float*)d_in[7];
    const float* Wl2 = (const float*)d_in[8];
    const float* b2  = (const float*)d_in[9];
    const float* Wr3 = (const float*)d_in[10];
    const float* Wl3 = (const float*)d_in[11];
    const float* b3  = (const float*)d_in[12];
    float* out = (float*)d_out;

    const int smem_bytes = NLOC * 4 * 2          // hist + cnt
                         + CAP * 2               // sadj (u16)
                         + 4 * 32 * WPAD * 4     // WT
                         + NW * 256 * 4          // zs
                         + NW * 32 * 4           // snode
                         + 64 * 4;               // biases
    cudaFuncSetAttribute(fused_kernel,
                         cudaFuncAttributeMaxDynamicSharedMemorySize, smem_bytes);

    fused_kernel<<<BG * SPLITS, 256, smem_bytes>>>(x, ei, Wr1, Wl1, b1,
                                                   Wr2, Wl2, b2);
    topk_kernel<<<BG, 1024>>>(out);
    edge_filter_kernel<<<(EE / 4) / 256, 256>>>(ei, ea, out);
    x3x5_kernel<<<BK / 32, 256>>>(x, Wr3, Wl3, b3, out);
}

// round 11
// speedup vs baseline: 1.5235x; 1.0573x over previous
#include <cuda_runtime.h>
#include <cuda_bf16.h>
#include <cstdint>
#include <climits>

// Problem constants
#define BG   64
#define NPG  2048
#define NN   (BG * NPG)      // 131072 nodes
#define EPG  32768
#define EE   (BG * EPG)      // 2097152 edges
#define DD   32
#define KK   1024            // kept per graph
#define BK   (BG * KK)       // 65536 kept total

#define SPLITS 8             // blocks per graph
#define NLOC   (NPG / SPLITS)   // 256 nodes per block
#define CAPN   48            // per-node adjacency slots (Poisson(16): P(d>48)~5e-11)
#define WPAD   36            // padded column stride (floats) for transposed weights
#define NW     8             // warps per fused block

// Output layout (flattened f32, reference return order)
#define OFF_X5     ((size_t)0)                       // BK*DD
#define OFF_EI     ((size_t)(BK * DD))               // 2*EE
#define OFF_EA     (OFF_EI + (size_t)(2 * EE))       // EE
#define OFF_BATCH  (OFF_EA + (size_t)EE)             // BK
#define OFF_PERM   (OFF_BATCH + (size_t)BK)          // BK
#define OFF_SCORE  (OFF_PERM + (size_t)BK)           // BK

// Scratch (device globals -- no allocation allowed)
__device__ float g_agg[(size_t)NN * DD];
__device__ float g_score[NN];
__device__ int   g_newidx[NN];
__device__ int   g_perm[BK];

typedef unsigned long long ull;

// packed f32x2 FMA: each 32-bit half is an independent IEEE fma.rn.f32
__device__ __forceinline__ void ffma2(ull& acc, ull w, ull z) {
    asm("fma.rn.f32x2 %0, %1, %2, %3;" : "=l"(acc) : "l"(w), "l"(z), "l"(acc));
}
__device__ __forceinline__ ull pack2(float v) {
    ull r;
    asm("mov.b64 %0, {%1, %2};" : "=l"(r) : "f"(v), "f"(v));
    return r;
}
__device__ __forceinline__ float2 unpack2(ull v) {
    float2 r;
    asm("mov.b64 {%0, %1}, %2;" : "=f"(r.x), "=f"(r.y) : "l"(v));
    return r;
}

// ---------------------------------------------------------------------------
// Fused: one-pass direct-slot CSR (smem) + edge-order aggregation + score.
// Block b: graph g = b/SPLITS, nodes [h*NLOC,(h+1)*NLOC), h = b%SPLITS.
// 256 threads (8 warps); warp handles 32 nodes in 8 groups of 4.
__global__ __launch_bounds__(256, 4) void fused_kernel(
    const float* __restrict__ x, const int* __restrict__ ei,
    const float* __restrict__ Wr1, const float* __restrict__ Wl1,
    const float* __restrict__ b1,
    const float* __restrict__ Wr2, const float* __restrict__ Wl2,
    const float* __restrict__ b2) {
    extern __shared__ int smem[];
    int*            cnt   = smem;                          // [NLOC]
    unsigned short* sadj  = (unsigned short*)(cnt + NLOC); // [NLOC*CAPN] u16 eids
    float*          WT    = (float*)(sadj + NLOC * CAPN);  // 4 * 32 * WPAD
    float*          zs    = WT + 4 * 32 * WPAD;            // NW warps * 256
    int*            snode = (int*)(zs + NW * 256);         // NW warps * 32
    float*          sb1   = (float*)(snode + NW * 32);     // 32
    float*          sb2   = sb1 + 32;                      // 32

    int t = threadIdx.x;
    int g = blockIdx.x / SPLITS;
    int h = blockIdx.x % SPLITS;
    int nbase = h * NLOC;
    int ebase = g * EPG;

    cnt[t] = 0;
    // transpose weights: WT[m][j*WPAD + k] = Wm[k*32 + j]
    for (int i = t; i < 1024; i += 256) {
        int k = i >> 5, j = i & 31;
        WT[(0 * 32 + j) * WPAD + k] = Wr1[i];
        WT[(1 * 32 + j) * WPAD + k] = Wl1[i];
        WT[(2 * 32 + j) * WPAD + k] = Wr2[i];
        WT[(3 * 32 + j) * WPAD + k] = Wl2[i];
    }
    if (t < 32) { sb1[t] = b1[t]; sb2[t] = b2[t]; }
    __syncthreads();

    // --- 1) single-pass placement into per-node fixed slots
    const int* dstp = ei + EE + ebase;
    for (int i = t; i < EPG; i += 256) {
        int dl = __ldg(&dstp[i]) - g * NPG - nbase;
        if ((unsigned)dl < (unsigned)NLOC) {
            int pos = atomicAdd(&cnt[dl], 1);
            if (pos < CAPN) sadj[dl * CAPN + pos] = (unsigned short)i;
        }
    }
    __syncthreads();

    // --- 2) 4-node groups: rank-order srcs, aggregate in edge order, score
    int w = t >> 5, lane = t & 31;
    const int* srcp = ei + ebase;
    float* zsw = zs + w * 256;    // [inp(2)][k(32)][u(4)]
    int*   sn  = snode + w * 32;

    for (int grp = 0; grp < 8; grp++) {
#pragma unroll
        for (int u = 0; u < 4; u++) {
            int nl = w * 32 + grp * 4 + u;
            int off = nl * CAPN;
            int d = min(cnt[nl], CAPN);
            int n = g * NPG + nbase + nl;

            float acc = 0.0f;
            if (d > 0 && d <= 32) {
                int eid = (lane < d) ? (int)sadj[off + lane] : INT_MAX;
                // rank = #(smaller eids); eids unique -> exact edge order
                int rank = 0;
#pragma unroll
                for (int j = 0; j < 32; j++)
                    rank += (int)(__shfl_sync(0xffffffffu, eid, j) < eid);
                int src = (lane < d) ? __ldg(&srcp[eid]) : 0;
                if (lane < d) sn[rank] = src;
                __syncwarp();
                // edge-order sequential adds; loads prefetched in batches of 16
                for (int b16 = 0; b16 < d; b16 += 16) {
                    float v[16];
#pragma unroll
                    for (int j = 0; j < 16; j++) {
                        v[j] = 0.0f;
                        if (b16 + j < d) {
                            int sj = sn[b16 + j];
                            v[j] = __ldg(&x[(size_t)sj * DD + lane]);
                        }
                    }
#pragma unroll
                    for (int j = 0; j < 16; j++)
                        if (b16 + j < d) acc = __fadd_rn(acc, v[j]);
                }
                __syncwarp();
            } else if (d > 32) {
                // rare fallback: sequential min-extraction (exact edge order)
                int cur = -1;
                for (int k = 0; k < d; k++) {
                    int m = INT_MAX;
                    for (int i = lane; i < d; i += 32) {
                        int e = (int)sadj[off + i];
                        if (e > cur && e < m) m = e;
                    }
#pragma unroll
                    for (int o = 16; o; o >>= 1)
                        m = min(m, __shfl_xor_sync(0xffffffffu, m, o));
                    int sj = __ldg(&srcp[m]);
                    acc = __fadd_rn(acc, __ldg(&x[(size_t)sj * DD + lane]));
                    cur = m;
                }
            }
            g_agg[(size_t)n * DD + lane] = acc;
            float xv = __ldg(&x[(size_t)n * DD + lane]);
            zsw[lane * 4 + u]       = xv;
            zsw[128 + lane * 4 + u] = acc;
        }
        __syncwarp();

        // GEMV: 4 nodes as 2 packed pairs, weights loaded once per group
        ull a1[2] = {0, 0}, c1[2] = {0, 0}, a2[2] = {0, 0}, c2[2] = {0, 0};
#pragma unroll
        for (int k4 = 0; k4 < 8; k4++) {
            float4 wr1 = *(const float4*)&WT[(0 * 32 + lane) * WPAD + k4 * 4];
            float4 wl1 = *(const float4*)&WT[(1 * 32 + lane) * WPAD + k4 * 4];
            float4 wr2 = *(const float4*)&WT[(2 * 32 + lane) * WPAD + k4 * 4];
            float4 wl2 = *(const float4*)&WT[(3 * 32 + lane) * WPAD + k4 * 4];
#define GEMV_STEP(KK, C)                                                     \
            {                                                                \
                int k = k4 * 4 + KK;                                         \
                ulonglong2 zx = *(const ulonglong2*)&zsw[k * 4];             \
                ulonglong2 za = *(const ulonglong2*)&zsw[128 + k * 4];       \
                ull wp;                                                      \
                wp = pack2(wr1.C); ffma2(a1[0], wp, zx.x); ffma2(a1[1], wp, zx.y); \
                wp = pack2(wl1.C); ffma2(c1[0], wp, za.x); ffma2(c1[1], wp, za.y); \
                wp = pack2(wr2.C); ffma2(a2[0], wp, zx.x); ffma2(a2[1], wp, zx.y); \
                wp = pack2(wl2.C); ffma2(c2[0], wp, za.x); ffma2(c2[1], wp, za.y); \
            }
            GEMV_STEP(0, x) GEMV_STEP(1, y) GEMV_STEP(2, z) GEMV_STEP(3, w)
#undef GEMV_STEP
        }
        __syncwarp();

        // epilogue: p = x2*y2 per (node, lane=j) staged for transpose reduce
#pragma unroll
        for (int pp = 0; pp < 2; pp++) {
            float2 A1 = unpack2(a1[pp]), C1 = unpack2(c1[pp]);
            float2 A2 = unpack2(a2[pp]), C2 = unpack2(c2[pp]);
            float x2l = __fadd_rn(__fadd_rn(A1.x, C1.x), sb1[lane]);
            float y2l = __fadd_rn(__fadd_rn(A2.x, C2.x), sb2[lane]);
            zsw[lane * 4 + pp * 2 + 0] = __fmul_rn(x2l, y2l);
            float x2h = __fadd_rn(__fadd_rn(A1.y, C1.y), sb1[lane]);
            float y2h = __fadd_rn(__fadd_rn(A2.y, C2.y), sb2[lane]);
            zsw[lane * 4 + pp * 2 + 1] = __fmul_rn(x2h, y2h);
        }
        __syncwarp();
        if (lane < 4) {
            // left-fold j = 0..31 (reference reduce order)
            float s = zsw[lane];
#pragma unroll
            for (int j = 1; j < 32; j++)
                s = __fadd_rn(s, zsw[j * 4 + lane]);
            int n = g * NPG + nbase + w * 32 + grp * 4 + lane;
            g_score[n] = __fdiv_rn(s, 5.656854249492380195e0f);  // f32 sqrt(32)
        }
        __syncwarp();
    }
}

// ---------------------------------------------------------------------------
// per-graph top-K via bitonic sort of 2048 keys (desc score, asc idx)
__global__ void topk_kernel(float* __restrict__ out) {
    __shared__ unsigned long long sk[NPG];
    int b = blockIdx.x;
    int t = threadIdx.x;     // 1024 threads
    int base = b * NPG;

    for (int i = t; i < NPG; i += 1024) {
        unsigned int bits = __float_as_uint(g_score[base + i]);
        unsigned int m = (bits & 0x80000000u) ? ~bits : (bits | 0x80000000u);
        unsigned int dm = ~m;    // descending order map
        sk[i] = ((unsigned long long)dm << 32) | (unsigned int)i;
    }
    __syncthreads();

    for (int k2 = 2; k2 <= NPG; k2 <<= 1) {
        for (int j = k2 >> 1; j >= 1; j >>= 1) {
            int i  = ((t & ~(j - 1)) << 1) | (t & (j - 1));
            int p2 = i | j;
            bool asc = ((i & k2) == 0);
            unsigned long long a = sk[i], c = sk[p2];
            if ((a > c) == asc) { sk[i] = c; sk[p2] = a; }
            __syncthreads();
        }
    }

    for (int p = t; p < NPG; p += 1024) {
        unsigned long long key = sk[p];
        int idx = (int)(key & 0xFFFFFFFFu);
        int g = base + idx;
        if (p < KK) {
            int r = b * KK + p;
            g_newidx[g] = r;
            g_perm[r]   = g;
            out[OFF_BATCH + r] = (float)b;
            out[OFF_PERM  + r] = (float)g;
            out[OFF_SCORE + r] = g_score[g];
        } else {
            g_newidx[g] = -1;
        }
    }
}

// ---------------------------------------------------------------------------
// filter_adj: 4 edges per thread; streaming stores (write-once output).
__global__ void edge_filter_kernel(const int* __restrict__ ei,
                                   const float* __restrict__ ea,
                                   float* __restrict__ out) {
    int e4 = blockIdx.x * blockDim.x + threadIdx.x;  // < EE/4
    int4 sp = __ldg((const int4*)ei + e4);
    int4 dp = __ldg((const int4*)(ei + EE) + e4);
    float4 av = __ldg((const float4*)ea + e4);
    int ns0 = g_newidx[sp.x], ns1 = g_newidx[sp.y];
    int ns2 = g_newidx[sp.z], ns3 = g_newidx[sp.w];
    int nd0 = g_newidx[dp.x], nd1 = g_newidx[dp.y];
    int nd2 = g_newidx[dp.z], nd3 = g_newidx[dp.w];
    bool v0 = (ns0 >= 0) && (nd0 >= 0);
    bool v1 = (ns1 >= 0) && (nd1 >= 0);
    bool v2 = (ns2 >= 0) && (nd2 >= 0);
    bool v3 = (ns3 >= 0) && (nd3 >= 0);
    float4 so = make_float4(v0 ? (float)ns0 : -1.0f, v1 ? (float)ns1 : -1.0f,
                            v2 ? (float)ns2 : -1.0f, v3 ? (float)ns3 : -1.0f);
    float4 dd = make_float4(v0 ? (float)nd0 : -1.0f, v1 ? (float)nd1 : -1.0f,
                            v2 ? (float)nd2 : -1.0f, v3 ? (float)nd3 : -1.0f);
    float4 ao = make_float4(v0 ? av.x : 0.0f, v1 ? av.y : 0.0f,
                            v2 ? av.z : 0.0f, v3 ? av.w : 0.0f);
    __stcs(&((float4*)(out + OFF_EI))[e4], so);
    __stcs(&((float4*)(out + OFF_EI + EE))[e4], dd);
    __stcs(&((float4*)(out + OFF_EA))[e4], ao);
}

// ---------------------------------------------------------------------------
// x3 + x5 fused, surviving nodes only: warp handles 16 kept nodes in 4
// groups of 4 (amortizes weight loads 4x vs R10). FFMA2 pairs.
__global__ __launch_bounds__(256, 4) void x3x5_kernel(
    const float* __restrict__ x,
    const float* __restrict__ Wr3, const float* __restrict__ Wl3,
    const float* __restrict__ b3,
    float* __restrict__ out) {
    __shared__ float WT[2 * 32 * WPAD];
    __shared__ float zs[8 * 256];
    __shared__ float sb3[32];
    int t = threadIdx.x;
    for (int i = t; i < 1024; i += 256) {
        int k = i >> 5, j = i & 31;
        WT[(0 * 32 + j) * WPAD + k] = Wr3[i];
        WT[(1 * 32 + j) * WPAD + k] = Wl3[i];
    }
    if (t < 32) sb3[t] = b3[t];
    __syncthreads();

    int w = t >> 5, lane = t & 31;
    float* zsw = zs + w * 256;

    for (int gi = 0; gi < 4; gi++) {
        int i0 = blockIdx.x * 128 + w * 16 + gi * 4;   // 4 kept nodes
        float xv[4], sc[4];
#pragma unroll
        for (int u = 0; u < 4; u++) {
            int p = g_perm[i0 + u];
            sc[u] = g_score[p];
            xv[u] = __ldg(&x[(size_t)p * DD + lane]);
            float av = g_agg[(size_t)p * DD + lane];
            zsw[lane * 4 + u]       = xv[u];
            zsw[128 + lane * 4 + u] = av;
        }
        __syncwarp();

        ull a[2] = {0, 0}, c[2] = {0, 0};
#pragma unroll
        for (int k4 = 0; k4 < 8; k4++) {
            float4 wr = *(const float4*)&WT[(0 * 32 + lane) * WPAD + k4 * 4];
            float4 wl = *(const float4*)&WT[(1 * 32 + lane) * WPAD + k4 * 4];
#define X3_STEP(KK, C)                                                       \
            {                                                                \
                int k = k4 * 4 + KK;                                         \
                ulonglong2 zx = *(const ulonglong2*)&zsw[k * 4];             \
                ulonglong2 za = *(const ulonglong2*)&zsw[128 + k * 4];       \
                ull wp;                                                      \
                wp = pack2(wr.C); ffma2(a[0], wp, zx.x); ffma2(a[1], wp, zx.y);  \
                wp = pack2(wl.C); ffma2(c[0], wp, za.x); ffma2(c[1], wp, za.y);  \
            }
            X3_STEP(0, x) X3_STEP(1, y) X3_STEP(2, z) X3_STEP(3, w)
#undef X3_STEP
        }

#pragma unroll
        for (int pp = 0; pp < 2; pp++) {
            float2 A = unpack2(a[pp]), C = unpack2(c[pp]);
            float x3l = __fadd_rn(__fadd_rn(A.x, C.x), sb3[lane]);
            float x3h = __fadd_rn(__fadd_rn(A.y, C.y), sb3[lane]);
            int ul = pp * 2, uh = pp * 2 + 1;
            __stcs(&out[OFF_X5 + (size_t)(i0 + ul) * DD + lane],
                   __fadd_rn(xv[ul], __fmul_rn(sc[ul], x3l)));
            __stcs(&out[OFF_X5 + (size_t)(i0 + uh) * DD + lane],
                   __fadd_rn(xv[uh], __fmul_rn(sc[uh], x3h)));
        }
        __syncwarp();
    }
}

// ---------------------------------------------------------------------------
extern "C" void kernel_launch(void* const* d_in, const int* in_sizes, int n_in,
                              void* d_out, int out_size) {
    const float* x    = (const float*)d_in[0];
    const int*   ei   = (const int*)  d_in[1];
    const float* ea   = (const float*)d_in[2];
    // d_in[3] = batch (unused: batch[perm] == graph id, computed directly)
    const float* Wr1 = (const float*)d_in[4];
    const float* Wl1 = (const float*)d_in[5];
    const float* b1  = (const float*)d_in[6];
    const float* Wr2 = (const float*)d_in[7];
    const float* Wl2 = (const float*)d_in[8];
    const float* b2  = (const float*)d_in[9];
    const float* Wr3 = (const float*)d_in[10];
    const float* Wl3 = (const float*)d_in[11];
    const float* b3  = (const float*)d_in[12];
    float* out = (float*)d_out;

    const int smem_bytes = NLOC * 4              // cnt
                         + NLOC * CAPN * 2       // sadj (u16, strided slots)
                         + 4 * 32 * WPAD * 4     // WT
                         + NW * 256 * 4          // zs
                         + NW * 32 * 4           // snode
                         + 64 * 4;               // biases
    cudaFuncSetAttribute(fused_kernel,
                         cudaFuncAttributeMaxDynamicSharedMemorySize, smem_bytes);

    fused_kernel<<<BG * SPLITS, 256, smem_bytes>>>(x, ei, Wr1, Wl1, b1,
                                                   Wr2, Wl2, b2);
    topk_kernel<<<BG, 1024>>>(out);
    edge_filter_kernel<<<(EE / 4) / 256, 256>>>(ei, ea, out);
    x3x5_kernel<<<BK / 128, 256>>>(x, Wr3, Wl3, b3, out);
}

// round 12
// speedup vs baseline: 1.5598x; 1.0238x over previous
#include <cuda_runtime.h>
#include <cuda_bf16.h>
#include <cstdint>
#include <climits>

// Problem constants
#define BG   64
#define NPG  2048
#define NN   (BG * NPG)      // 131072 nodes
#define EPG  32768
#define EE   (BG * EPG)      // 2097152 edges
#define DD   32
#define KK   1024            // kept per graph
#define BK   (BG * KK)       // 65536 kept total

#define SPLITS 8             // blocks per graph
#define NLOC   (NPG / SPLITS)   // 256 nodes per block
#define CAPN   48            // per-node adjacency slots (Poisson(16): P(d>48)~5e-11)
#define WPAD   36            // padded column stride (floats) for transposed weights
#define NW     8             // warps per fused block

// Output layout (flattened f32, reference return order)
#define OFF_X5     ((size_t)0)                       // BK*DD
#define OFF_EI     ((size_t)(BK * DD))               // 2*EE
#define OFF_EA     (OFF_EI + (size_t)(2 * EE))       // EE
#define OFF_BATCH  (OFF_EA + (size_t)EE)             // BK
#define OFF_PERM   (OFF_BATCH + (size_t)BK)          // BK
#define OFF_SCORE  (OFF_PERM + (size_t)BK)           // BK

// Scratch (device globals -- no allocation allowed)
__device__ float g_agg[(size_t)NN * DD];
__device__ float g_score[NN];
__device__ int   g_newidx[NN];
__device__ int   g_perm[BK];

typedef unsigned long long ull;

// packed f32x2 FMA: each 32-bit half is an independent IEEE fma.rn.f32
__device__ __forceinline__ void ffma2(ull& acc, ull w, ull z) {
    asm("fma.rn.f32x2 %0, %1, %2, %3;" : "=l"(acc) : "l"(w), "l"(z), "l"(acc));
}
__device__ __forceinline__ ull pack2(float v) {
    ull r;
    asm("mov.b64 %0, {%1, %2};" : "=l"(r) : "f"(v), "f"(v));
    return r;
}
__device__ __forceinline__ float2 unpack2(ull v) {
    float2 r;
    asm("mov.b64 {%0, %1}, %2;" : "=f"(r.x), "=f"(r.y) : "l"(v));
    return r;
}

// ---------------------------------------------------------------------------
// Fused: one-pass direct-slot CSR (smem) + edge-order aggregation + score.
// Block b: graph g = b/SPLITS, nodes [h*NLOC,(h+1)*NLOC), h = b%SPLITS.
// 256 threads (8 warps); warp handles 32 nodes in 8 groups of 4,
// software-pipelined: phase A builds all 4 src lists, phase B overlaps the
// 4 nodes' gathers and runs 4 independent sequential add chains.
__global__ __launch_bounds__(256, 4) void fused_kernel(
    const float* __restrict__ x, const int* __restrict__ ei,
    const float* __restrict__ Wr1, const float* __restrict__ Wl1,
    const float* __restrict__ b1,
    const float* __restrict__ Wr2, const float* __restrict__ Wl2,
    const float* __restrict__ b2) {
    extern __shared__ int smem[];
    int*            cnt   = smem;                          // [NLOC]
    unsigned short* sadj  = (unsigned short*)(cnt + NLOC); // [NLOC*CAPN] u16 eids
    float*          WT    = (float*)(sadj + NLOC * CAPN);  // 4 * 32 * WPAD
    float*          zs    = WT + 4 * 32 * WPAD;            // NW warps * 256
    int*            snode = (int*)(zs + NW * 256);         // NW warps * 128
    float*          sb1   = (float*)(snode + NW * 128);    // 32
    float*          sb2   = sb1 + 32;                      // 32

    int t = threadIdx.x;
    int g = blockIdx.x / SPLITS;
    int h = blockIdx.x % SPLITS;
    int nbase = h * NLOC;
    int ebase = g * EPG;

    cnt[t] = 0;
    // transpose weights: WT[m][j*WPAD + k] = Wm[k*32 + j]
    for (int i = t; i < 1024; i += 256) {
        int k = i >> 5, j = i & 31;
        WT[(0 * 32 + j) * WPAD + k] = Wr1[i];
        WT[(1 * 32 + j) * WPAD + k] = Wl1[i];
        WT[(2 * 32 + j) * WPAD + k] = Wr2[i];
        WT[(3 * 32 + j) * WPAD + k] = Wl2[i];
    }
    if (t < 32) { sb1[t] = b1[t]; sb2[t] = b2[t]; }
    __syncthreads();

    // --- 1) single-pass placement into per-node fixed slots
    const int* dstp = ei + EE + ebase;
    for (int i = t; i < EPG; i += 256) {
        int dl = __ldg(&dstp[i]) - g * NPG - nbase;
        if ((unsigned)dl < (unsigned)NLOC) {
            int pos = atomicAdd(&cnt[dl], 1);
            if (pos < CAPN) sadj[dl * CAPN + pos] = (unsigned short)i;
        }
    }
    __syncthreads();

    // --- 2) 4-node groups, pipelined
    int w = t >> 5, lane = t & 31;
    const int* srcp = ei + ebase;
    float* zsw = zs + w * 256;     // [inp(2)][k(32)][u(4)]
    int*   sn  = snode + w * 128;  // 4 nodes x 32 src slots

    for (int grp = 0; grp < 8; grp++) {
        int nl0 = w * 32 + grp * 4;
        int d[4], dd[4];

        // phase A: build rank-permuted src lists for all 4 nodes
#pragma unroll
        for (int u = 0; u < 4; u++) {
            int nl = nl0 + u;
            d[u] = min(cnt[nl], CAPN);
            dd[u] = (d[u] <= 32) ? d[u] : 0;
            if (dd[u] > 0) {
                int eid = (lane < dd[u]) ? (int)sadj[nl * CAPN + lane] : INT_MAX;
                int rank = 0;
#pragma unroll
                for (int j = 0; j < 32; j++)
                    rank += (int)(__shfl_sync(0xffffffffu, eid, j) < eid);
                if (lane < dd[u]) sn[u * 32 + rank] = __ldg(&srcp[eid]);
            }
        }
        __syncwarp();

        // phase B: interleaved gather + 4 independent sequential add chains
        float acc[4] = {0.f, 0.f, 0.f, 0.f};
        float xn[4];
#pragma unroll
        for (int u = 0; u < 4; u++)
            xn[u] = __ldg(&x[(size_t)(g * NPG + nbase + nl0 + u) * DD + lane]);

        int dmax = max(max(dd[0], dd[1]), max(dd[2], dd[3]));
        for (int jb = 0; jb < dmax; jb += 4) {
            float v[16];
#pragma unroll
            for (int j = 0; j < 4; j++) {
#pragma unroll
                for (int u = 0; u < 4; u++) {
                    int idx = jb + j;
                    v[j * 4 + u] = 0.0f;
                    if (idx < dd[u]) {
                        int sj = sn[u * 32 + idx];
                        v[j * 4 + u] = __ldg(&x[(size_t)sj * DD + lane]);
                    }
                }
            }
            // padding adds are +0.0f: exact identity (acc is never -0 here)
#pragma unroll
            for (int j = 0; j < 4; j++)
#pragma unroll
                for (int u = 0; u < 4; u++)
                    acc[u] = __fadd_rn(acc[u], v[j * 4 + u]);
        }

        // rare fallback: d in (32, CAPN]: exact sequential min-extraction
#pragma unroll
        for (int u = 0; u < 4; u++) {
            if (d[u] > 32) {
                int off = (nl0 + u) * CAPN;
                float a = 0.0f;
                int cur = -1;
                for (int k = 0; k < d[u]; k++) {
                    int m = INT_MAX;
                    for (int i = lane; i < d[u]; i += 32) {
                        int e = (int)sadj[off + i];
                        if (e > cur && e < m) m = e;
                    }
#pragma unroll
                    for (int o = 16; o; o >>= 1)
                        m = min(m, __shfl_xor_sync(0xffffffffu, m, o));
                    a = __fadd_rn(a, __ldg(&x[(size_t)__ldg(&srcp[m]) * DD + lane]));
                    cur = m;
                }
                acc[u] = a;
            }
        }

        // stage z and store agg
#pragma unroll
        for (int u = 0; u < 4; u++) {
            int n = g * NPG + nbase + nl0 + u;
            g_agg[(size_t)n * DD + lane] = acc[u];
            zsw[lane * 4 + u]       = xn[u];
            zsw[128 + lane * 4 + u] = acc[u];
        }
        __syncwarp();

        // GEMV: 4 nodes as 2 packed pairs, weights loaded once per group
        ull a1[2] = {0, 0}, c1[2] = {0, 0}, a2[2] = {0, 0}, c2[2] = {0, 0};
#pragma unroll
        for (int k4 = 0; k4 < 8; k4++) {
            float4 wr1 = *(const float4*)&WT[(0 * 32 + lane) * WPAD + k4 * 4];
            float4 wl1 = *(const float4*)&WT[(1 * 32 + lane) * WPAD + k4 * 4];
            float4 wr2 = *(const float4*)&WT[(2 * 32 + lane) * WPAD + k4 * 4];
            float4 wl2 = *(const float4*)&WT[(3 * 32 + lane) * WPAD + k4 * 4];
#define GEMV_STEP(KK, C)                                                     \
            {                                                                \
                int k = k4 * 4 + KK;                                         \
                ulonglong2 zx = *(const ulonglong2*)&zsw[k * 4];             \
                ulonglong2 za = *(const ulonglong2*)&zsw[128 + k * 4];       \
                ull wp;                                                      \
                wp = pack2(wr1.C); ffma2(a1[0], wp, zx.x); ffma2(a1[1], wp, zx.y); \
                wp = pack2(wl1.C); ffma2(c1[0], wp, za.x); ffma2(c1[1], wp, za.y); \
                wp = pack2(wr2.C); ffma2(a2[0], wp, zx.x); ffma2(a2[1], wp, zx.y); \
                wp = pack2(wl2.C); ffma2(c2[0], wp, za.x); ffma2(c2[1], wp, za.y); \
            }
            GEMV_STEP(0, x) GEMV_STEP(1, y) GEMV_STEP(2, z) GEMV_STEP(3, w)
#undef GEMV_STEP
        }
        __syncwarp();

        // epilogue: p = x2*y2 per (node, lane=j) staged for transpose reduce
#pragma unroll
        for (int pp = 0; pp < 2; pp++) {
            float2 A1 = unpack2(a1[pp]), C1 = unpack2(c1[pp]);
            float2 A2 = unpack2(a2[pp]), C2 = unpack2(c2[pp]);
            float x2l = __fadd_rn(__fadd_rn(A1.x, C1.x), sb1[lane]);
            float y2l = __fadd_rn(__fadd_rn(A2.x, C2.x), sb2[lane]);
            zsw[lane * 4 + pp * 2 + 0] = __fmul_rn(x2l, y2l);
            float x2h = __fadd_rn(__fadd_rn(A1.y, C1.y), sb1[lane]);
            float y2h = __fadd_rn(__fadd_rn(A2.y, C2.y), sb2[lane]);
            zsw[lane * 4 + pp * 2 + 1] = __fmul_rn(x2h, y2h);
        }
        __syncwarp();
        if (lane < 4) {
            // left-fold j = 0..31 (reference reduce order)
            float s = zsw[lane];
#pragma unroll
            for (int j = 1; j < 32; j++)
                s = __fadd_rn(s, zsw[j * 4 + lane]);
            int n = g * NPG + nbase + nl0 + lane;
            g_score[n] = __fdiv_rn(s, 5.656854249492380195e0f);  // f32 sqrt(32)
        }
        __syncwarp();
    }
}

// ---------------------------------------------------------------------------
// per-graph top-K via bitonic sort of 2048 keys (desc score, asc idx)
__global__ void topk_kernel(float* __restrict__ out) {
    __shared__ unsigned long long sk[NPG];
    int b = blockIdx.x;
    int t = threadIdx.x;     // 1024 threads
    int base = b * NPG;

    for (int i = t; i < NPG; i += 1024) {
        unsigned int bits = __float_as_uint(g_score[base + i]);
        unsigned int m = (bits & 0x80000000u) ? ~bits : (bits | 0x80000000u);
        unsigned int dm = ~m;    // descending order map
        sk[i] = ((unsigned long long)dm << 32) | (unsigned int)i;
    }
    __syncthreads();

    for (int k2 = 2; k2 <= NPG; k2 <<= 1) {
        for (int j = k2 >> 1; j >= 1; j >>= 1) {
            int i  = ((t & ~(j - 1)) << 1) | (t & (j - 1));
            int p2 = i | j;
            bool asc = ((i & k2) == 0);
            unsigned long long a = sk[i], c = sk[p2];
            if ((a > c) == asc) { sk[i] = c; sk[p2] = a; }
            __syncthreads();
        }
    }

    for (int p = t; p < NPG; p += 1024) {
        unsigned long long key = sk[p];
        int idx = (int)(key & 0xFFFFFFFFu);
        int g = base + idx;
        if (p < KK) {
            int r = b * KK + p;
            g_newidx[g] = r;
            g_perm[r]   = g;
            out[OFF_BATCH + r] = (float)b;
            out[OFF_PERM  + r] = (float)g;
            out[OFF_SCORE + r] = g_score[g];
        } else {
            g_newidx[g] = -1;
        }
    }
}

// ---------------------------------------------------------------------------
// filter_adj: 4 edges per thread; streaming stores (write-once output).
__global__ void edge_filter_kernel(const int* __restrict__ ei,
                                   const float* __restrict__ ea,
                                   float* __restrict__ out) {
    int e4 = blockIdx.x * blockDim.x + threadIdx.x;  // < EE/4
    int4 sp = __ldg((const int4*)ei + e4);
    int4 dp = __ldg((const int4*)(ei + EE) + e4);
    float4 av = __ldg((const float4*)ea + e4);
    int ns0 = g_newidx[sp.x], ns1 = g_newidx[sp.y];
    int ns2 = g_newidx[sp.z], ns3 = g_newidx[sp.w];
    int nd0 = g_newidx[dp.x], nd1 = g_newidx[dp.y];
    int nd2 = g_newidx[dp.z], nd3 = g_newidx[dp.w];
    bool v0 = (ns0 >= 0) && (nd0 >= 0);
    bool v1 = (ns1 >= 0) && (nd1 >= 0);
    bool v2 = (ns2 >= 0) && (nd2 >= 0);
    bool v3 = (ns3 >= 0) && (nd3 >= 0);
    float4 so = make_float4(v0 ? (float)ns0 : -1.0f, v1 ? (float)ns1 : -1.0f,
                            v2 ? (float)ns2 : -1.0f, v3 ? (float)ns3 : -1.0f);
    float4 dd = make_float4(v0 ? (float)nd0 : -1.0f, v1 ? (float)nd1 : -1.0f,
                            v2 ? (float)nd2 : -1.0f, v3 ? (float)nd3 : -1.0f);
    float4 ao = make_float4(v0 ? av.x : 0.0f, v1 ? av.y : 0.0f,
                            v2 ? av.z : 0.0f, v3 ? av.w : 0.0f);
    __stcs(&((float4*)(out + OFF_EI))[e4], so);
    __stcs(&((float4*)(out + OFF_EI + EE))[e4], dd);
    __stcs(&((float4*)(out + OFF_EA))[e4], ao);
}

// ---------------------------------------------------------------------------
// x3 + x5 fused, surviving nodes only: warp handles 8 kept nodes in 2
// groups of 4, with next-group loads prefetched past the current GEMV.
__global__ __launch_bounds__(256, 4) void x3x5_kernel(
    const float* __restrict__ x,
    const float* __restrict__ Wr3, const float* __restrict__ Wl3,
    const float* __restrict__ b3,
    float* __restrict__ out) {
    __shared__ float WT[2 * 32 * WPAD];
    __shared__ float zs[8 * 256];
    __shared__ float sb3[32];
    int t = threadIdx.x;
    for (int i = t; i < 1024; i += 256) {
        int k = i >> 5, j = i & 31;
        WT[(0 * 32 + j) * WPAD + k] = Wr3[i];
        WT[(1 * 32 + j) * WPAD + k] = Wl3[i];
    }
    if (t < 32) sb3[t] = b3[t];
    __syncthreads();

    int w = t >> 5, lane = t & 31;
    float* zsw = zs + w * 256;
    int ibase = blockIdx.x * 64 + w * 8;   // 8 kept nodes per warp

    float xv[4], av[4], sc[4];
#pragma unroll
    for (int u = 0; u < 4; u++) {
        int p = g_perm[ibase + u];
        sc[u] = g_score[p];
        xv[u] = __ldg(&x[(size_t)p * DD + lane]);
        av[u] = g_agg[(size_t)p * DD + lane];
    }

#pragma unroll
    for (int gi = 0; gi < 2; gi++) {
        int i0 = ibase + gi * 4;
#pragma unroll
        for (int u = 0; u < 4; u++) {
            zsw[lane * 4 + u]       = xv[u];
            zsw[128 + lane * 4 + u] = av[u];
        }
        // prefetch next group before the GEMV consumes smem
        float nxv[4], nav[4], nsc[4];
        if (gi < 1) {
#pragma unroll
            for (int u = 0; u < 4; u++) {
                int p = g_perm[i0 + 4 + u];
                nsc[u] = g_score[p];
                nxv[u] = __ldg(&x[(size_t)p * DD + lane]);
                nav[u] = g_agg[(size_t)p * DD + lane];
            }
        }
        __syncwarp();

        ull a[2] = {0, 0}, c[2] = {0, 0};
#pragma unroll
        for (int k4 = 0; k4 < 8; k4++) {
            float4 wr = *(const float4*)&WT[(0 * 32 + lane) * WPAD + k4 * 4];
            float4 wl = *(const float4*)&WT[(1 * 32 + lane) * WPAD + k4 * 4];
#define X3_STEP(KK, C)                                                       \
            {                                                                \
                int k = k4 * 4 + KK;                                         \
                ulonglong2 zx = *(const ulonglong2*)&zsw[k * 4];             \
                ulonglong2 za = *(const ulonglong2*)&zsw[128 + k * 4];       \
                ull wp;                                                      \
                wp = pack2(wr.C); ffma2(a[0], wp, zx.x); ffma2(a[1], wp, zx.y);  \
                wp = pack2(wl.C); ffma2(c[0], wp, za.x); ffma2(c[1], wp, za.y);  \
            }
            X3_STEP(0, x) X3_STEP(1, y) X3_STEP(2, z) X3_STEP(3, w)
#undef X3_STEP
        }

#pragma unroll
        for (int pp = 0; pp < 2; pp++) {
            float2 A = unpack2(a[pp]), C = unpack2(c[pp]);
            float x3l = __fadd_rn(__fadd_rn(A.x, C.x), sb3[lane]);
            float x3h = __fadd_rn(__fadd_rn(A.y, C.y), sb3[lane]);
            int ul = pp * 2, uh = pp * 2 + 1;
            __stcs(&out[OFF_X5 + (size_t)(i0 + ul) * DD + lane],
                   __fadd_rn(xv[ul], __fmul_rn(sc[ul], x3l)));
            __stcs(&out[OFF_X5 + (size_t)(i0 + uh) * DD + lane],
                   __fadd_rn(xv[uh], __fmul_rn(sc[uh], x3h)));
        }
        __syncwarp();
#pragma unroll
        for (int u = 0; u < 4; u++) { xv[u] = nxv[u]; av[u] = nav[u]; sc[u] = nsc[u]; }
    }
}

// ---------------------------------------------------------------------------
extern "C" void kernel_launch(void* const* d_in, const int* in_sizes, int n_in,
                              void* d_out, int out_size) {
    const float* x    = (const float*)d_in[0];
    const int*   ei   = (const int*)  d_in[1];
    const float* ea   = (const float*)d_in[2];
    // d_in[3] = batch (unused: batch[perm] == graph id, computed directly)
    const float* Wr1 = (const float*)d_in[4];
    const float* Wl1 = (const float*)d_in[5];
    const float* b1  = (const float*)d_in[6];
    const float* Wr2 = (const float*)d_in[7];
    const float* Wl2 = (const float*)d_in[8];
    const float* b2  = (const float*)d_in[9];
    const float* Wr3 = (const float*)d_in[10];
    const float* Wl3 = (const float*)d_in[11];
    const float* b3  = (const float*)d_in[12];
    float* out = (float*)d_out;

    const int smem_bytes = NLOC * 4              // cnt
                         + NLOC * CAPN * 2       // sadj (u16, strided slots)
                         + 4 * 32 * WPAD * 4     // WT
                         + NW * 256 * 4          // zs
                         + NW * 128 * 4          // snode (4 nodes x 32)
                         + 64 * 4;               // biases
    cudaFuncSetAttribute(fused_kernel,
                         cudaFuncAttributeMaxDynamicSharedMemorySize, smem_bytes);

    fused_kernel<<<BG * SPLITS, 256, smem_bytes>>>(x, ei, Wr1, Wl1, b1,
                                                   Wr2, Wl2, b2);
    topk_kernel<<<BG, 1024>>>(out);
    edge_filter_kernel<<<(EE / 4) / 256, 256>>>(ei, ea, out);
    x3x5_kernel<<<BK / 64, 256>>>(x, Wr3, Wl3, b3, out);
}